// round 12
// baseline (speedup 1.0000x reference)
#include <cuda_runtime.h>
#include <cuda_fp16.h>
#include <math.h>
#include <cstdint>

// ---------------- problem constants ----------------
constexpr int BB     = 2;
constexpr int SEQ    = 2048;
constexpr int DMODEL = 2048;
constexpr int NH     = 16;
constexpr int NKV    = 4;
constexpr int HD     = 128;
constexpr int MROWS  = BB * SEQ;     // 4096
constexpr int QE     = NH * HD;      // 2048
constexpr int KVE    = NKV * HD;     // 512
constexpr int K2     = 4096;         // x stored as [hi(2048) | lo(2048)]
constexpr int NCH    = 64;           // k-chunks of 32 over DMODEL

// ---------------- scratch ----------------
__device__ __half g_x2 [(size_t)MROWS * K2];    // [xh | xl]
__device__ __half g_ao2[(size_t)MROWS * K2];    // [aoh | aol]
__device__ __half g_wqh[(size_t)QE     * DMODEL];
__device__ __half g_wkh[(size_t)KVE    * DMODEL];
__device__ __half g_wvh[(size_t)KVE    * DMODEL];
__device__ __half g_woh[(size_t)DMODEL * DMODEL];

__device__ __half g_qh2[(size_t)MROWS * QE];
__device__ __half g_ql2[(size_t)MROWS * QE];
__device__ __half g_kh2[(size_t)MROWS * KVE];
__device__ __half g_vh2[(size_t)MROWS * KVE];

// ---------------- helpers ----------------
__device__ __forceinline__ uint32_t smem_u32(const void* p) {
    uint32_t a;
    asm("{ .reg .u64 t; cvta.to.shared.u64 t, %1; cvt.u32.u64 %0, t; }"
        : "=r"(a) : "l"(p));
    return a;
}
__device__ __forceinline__ void cp16(uint32_t dst, const void* src) {
    asm volatile("cp.async.cg.shared.global [%0], [%1], 16;"
                 :: "r"(dst), "l"(src));
}
__device__ __forceinline__ void ldsm_x4(uint32_t* r, uint32_t addr) {
    asm volatile("ldmatrix.sync.aligned.m8n8.x4.shared.b16 {%0,%1,%2,%3}, [%4];"
                 : "=r"(r[0]), "=r"(r[1]), "=r"(r[2]), "=r"(r[3]) : "r"(addr));
}
__device__ __forceinline__ void ldsm_x4_t(uint32_t* r, uint32_t addr) {
    asm volatile("ldmatrix.sync.aligned.m8n8.x4.trans.shared.b16 {%0,%1,%2,%3}, [%4];"
                 : "=r"(r[0]), "=r"(r[1]), "=r"(r[2]), "=r"(r[3]) : "r"(addr));
}
__device__ __forceinline__ void mma_f16(float* d, const uint32_t* a,
                                        const uint32_t* b) {
    asm volatile(
        "mma.sync.aligned.m16n8k16.row.col.f32.f16.f16.f32 "
        "{%0,%1,%2,%3}, {%4,%5,%6,%7}, {%8,%9}, {%0,%1,%2,%3};"
        : "+f"(d[0]), "+f"(d[1]), "+f"(d[2]), "+f"(d[3])
        : "r"(a[0]), "r"(a[1]), "r"(a[2]), "r"(a[3]), "r"(b[0]), "r"(b[1]));
}
__device__ __forceinline__ uint32_t pack_f16(float lo, float hi) {
    uint32_t r;
    asm("cvt.rn.f16x2.f32 %0, %1, %2;" : "=r"(r) : "f"(hi), "f"(lo));
    return r;
}
__device__ __forceinline__ void split2h(float x, float y, uint32_t& hi, uint32_t& lo) {
    uint32_t h = pack_f16(x, y);
    __half2 hb = *reinterpret_cast<__half2*>(&h);
    lo = pack_f16(x - __half2float(hb.x), y - __half2float(hb.y));
    hi = h;
}

// ============================================================================
// merged conversion kernel
// ============================================================================
constexpr size_t CQ_X  = 2097152;
constexpr size_t CQ_WQ = CQ_X  + 1048576;
constexpr size_t CQ_WK = CQ_WQ + 262144;
constexpr size_t CQ_WV = CQ_WK + 262144;
constexpr size_t CQ_WO = CQ_WV + 1048576;

__global__ __launch_bounds__(256)
void convert_all(const float4* __restrict__ x,  const float4* __restrict__ wq,
                 const float4* __restrict__ wk, const float4* __restrict__ wv,
                 const float4* __restrict__ wo,
                 __half* __restrict__ x2,  __half* __restrict__ wqh,
                 __half* __restrict__ wkh, __half* __restrict__ wvh,
                 __half* __restrict__ woh)
{
    size_t i = (size_t)blockIdx.x * 256 + threadIdx.x;
    if (i < CQ_X) {
        float4 v = x[i];
        size_t e = i * 4;
        size_t r = e >> 11;
        int    c = (int)(e & 2047);
        float xs[4] = {v.x, v.y, v.z, v.w};
        __half* d = x2 + r * (size_t)K2 + c;
        #pragma unroll
        for (int j = 0; j < 4; j++) {
            __half h = __float2half(xs[j]);
            d[j]          = h;
            d[DMODEL + j] = __float2half(xs[j] - __half2float(h));
        }
        return;
    }
    const float4* src; __half* dst; size_t j;
    if      (i < CQ_WQ) { src = wq; dst = wqh; j = i - CQ_X;  }
    else if (i < CQ_WK) { src = wk; dst = wkh; j = i - CQ_WQ; }
    else if (i < CQ_WV) { src = wv; dst = wvh; j = i - CQ_WK; }
    else                { src = wo; dst = woh; j = i - CQ_WV; }
    float4 v = src[j];
    size_t e = j * 4;
    dst[e]     = __float2half(v.x);
    dst[e + 1] = __float2half(v.y);
    dst[e + 2] = __float2half(v.z);
    dst[e + 3] = __float2half(v.w);
}

// ============================================================================
// GEMM config — hi/lo-fused chunks: each k-chunk loads {Ah, Al, B} once and
// accumulates (Ah + Al)·B. B is loaded ONCE per k (was twice), ldsm drops to
// 96 B/MMA, barrier count halves. 3-stage ring, 2 CTAs/SM.
// ============================================================================
constexpr int HROWB  = 80;                 // bytes per smem row (40 halves)
constexpr int GTILE  = 128 * HROWB;        // 10240 B
constexpr int GSTAGE = 3 * GTILE;          // Ah + Al + B   = 30720 B
constexpr int GEMM16_SMEM = 3 * GSTAGE;    // 3 stages      = 92160 B

template <typename EPI>
__device__ __forceinline__
void gemm16_body(const __half* __restrict__ A, const __half* __restrict__ Bw,
                 int m0, int n0loc, EPI epi)
{
    extern __shared__ char sm[];
    const uint32_t sb = smem_u32(sm);
    const int tid = threadIdx.x;
    const int wid = tid >> 5;
    const int lane = tid & 31;
    const int wm = (wid >> 1) * 64;    // warp m offset (0/64)
    const int wn = (wid & 1) * 64;     // warp n offset (0/64)

    const __half* Abase = A  + (size_t)m0 * K2;
    const __half* Bbase = Bw + (size_t)n0loc * DMODEL;

    const int grp = lane >> 3, lr = lane & 7;
    const uint32_t aoff0 = (wm + (grp & 1) * 8 + lr) * HROWB + (grp >> 1) * 16;
    const uint32_t boff0 = 2 * GTILE + (wn + (grp >> 1) * 8 + lr) * HROWB
                         + (grp & 1) * 16;

    float acc[4][8][4];
    #pragma unroll
    for (int mf = 0; mf < 4; mf++)
        #pragma unroll
        for (int nf = 0; nf < 8; nf++)
            #pragma unroll
            for (int e = 0; e < 4; e++) acc[mf][nf][e] = 0.f;

    auto issue = [&](int c) {
        if (c >= NCH) return;
        const uint32_t st = sb + (c % 3) * GSTAGE;
        const __half* Ah = Abase + c * 32;             // hi half
        const __half* Al = Abase + DMODEL + c * 32;    // lo half
        const __half* Bg = Bbase + c * 32;
        #pragma unroll
        for (int t = 0; t < 4; t++) {
            int i = tid + t * 128;
            int row = i >> 2, seg = i & 3;
            cp16(st + row * HROWB + seg * 16,
                 Ah + (size_t)row * K2 + seg * 8);
            cp16(st + GTILE + row * HROWB + seg * 16,
                 Al + (size_t)row * K2 + seg * 8);
            cp16(st + 2 * GTILE + row * HROWB + seg * 16,
                 Bg + (size_t)row * DMODEL + seg * 8);
        }
    };

    issue(0); asm volatile("cp.async.commit_group;" ::: "memory");
    issue(1); asm volatile("cp.async.commit_group;" ::: "memory");

    uint32_t ah[4][4], al[4][4], br[4][4];

    for (int c = 0; c < NCH; c++) {
        asm volatile("cp.async.wait_group 1;" ::: "memory"); // stage c done
        __syncthreads();        // stage c visible to all; stage c-1 fully read
        issue(c + 2);           // overwrite stage (c-1)%3 (safe per barrier)
        asm volatile("cp.async.commit_group;" ::: "memory");

        const uint32_t st = sb + (c % 3) * GSTAGE;
        #pragma unroll
        for (int s = 0; s < 2; s++) {
            const uint32_t koff = s * 32;
            #pragma unroll
            for (int mf = 0; mf < 4; mf++) {
                ldsm_x4(ah[mf], st + aoff0 + mf * (16 * HROWB) + koff);
                ldsm_x4(al[mf], st + GTILE + aoff0 + mf * (16 * HROWB) + koff);
            }
            #pragma unroll
            for (int nf2 = 0; nf2 < 4; nf2++)
                ldsm_x4(br[nf2], st + boff0 + nf2 * (16 * HROWB) + koff);
            #pragma unroll
            for (int mf = 0; mf < 4; mf++)
                #pragma unroll
                for (int nf = 0; nf < 8; nf++) {
                    mma_f16(acc[mf][nf], ah[mf], &br[nf >> 1][(nf & 1) * 2]);
                    mma_f16(acc[mf][nf], al[mf], &br[nf >> 1][(nf & 1) * 2]);
                }
        }
    }

    const int lr4 = lane >> 2, lc2 = (lane & 3) * 2;
    #pragma unroll
    for (int mf = 0; mf < 4; mf++) {
        int r = m0 + wm + mf * 16 + lr4;
        #pragma unroll
        for (int nf = 0; nf < 8; nf++) {
            int cc = wn + nf * 8 + lc2;
            epi(r,     cc, acc[mf][nf][0], acc[mf][nf][1]);
            epi(r + 8, cc, acc[mf][nf][2], acc[mf][nf][3]);
        }
    }
}

// ============================================================================
// fused QKV projection (epilogue: RoPE + fp16 split)
// ============================================================================
__global__ __launch_bounds__(128, 2)
void qkv_gemm(const __half* __restrict__ x2,
              const __half* __restrict__ wqh, const __half* __restrict__ wkh,
              const __half* __restrict__ wvh,
              const float* __restrict__ fc, const float* __restrict__ fs,
              __half* __restrict__ qh2, __half* __restrict__ ql2,
              __half* __restrict__ kh2, __half* __restrict__ vh2)
{
    const int bx = blockIdx.x;
    const int m0 = blockIdx.y * 128;

    if (bx < 16) {
        const int n0 = bx * 128;
        gemm16_body(x2, wqh, m0, n0,
            [&](int r, int cc, float e, float o) {
                int col = n0 + cc;
                int s = r & (SEQ - 1);
                int p = (col & 127) >> 1;
                float c  = fc[s * 64 + p];
                float si = fs[s * 64 + p];
                float re = e * c - o * si;
                float ro = e * si + o * c;
                uint32_t hi, lo;
                split2h(re, ro, hi, lo);
                size_t idx = (size_t)r * QE + col;
                *(uint32_t*)(qh2 + idx) = hi;
                *(uint32_t*)(ql2 + idx) = lo;
            });
    } else if (bx < 20) {
        const int n0 = (bx - 16) * 128;
        gemm16_body(x2, wkh, m0, n0,
            [&](int r, int cc, float e, float o) {
                int col = n0 + cc;
                int s = r & (SEQ - 1);
                int p = (col & 127) >> 1;
                float c  = fc[s * 64 + p];
                float si = fs[s * 64 + p];
                float re = e * c - o * si;
                float ro = e * si + o * c;
                *(uint32_t*)(kh2 + (size_t)r * KVE + col) = pack_f16(re, ro);
            });
    } else {
        const int n0 = (bx - 20) * 128;
        gemm16_body(x2, wvh, m0, n0,
            [&](int r, int cc, float e, float o) {
                *(uint32_t*)(vh2 + (size_t)r * KVE + n0 + cc) = pack_f16(e, o);
            });
    }
}

// ============================================================================
// output projection
// ============================================================================
__global__ __launch_bounds__(128, 2)
void wo_gemm(const __half* __restrict__ ao2, const __half* __restrict__ woh,
             float* __restrict__ out)
{
    const int n0 = blockIdx.x * 128;
    const int m0 = blockIdx.y * 128;
    gemm16_body(ao2, woh, m0, n0,
        [&](int r, int cc, float e, float o) {
            *(float2*)(out + (size_t)r * DMODEL + n0 + cc) = make_float2(e, o);
        });
}

// ============================================================================
// fp16 2-term tensor-core causal flash attention (Br=128, Bc=64)
// (unchanged from R11 passing version)
// ============================================================================
constexpr int ATT_STRIDE = 136;
constexpr int ROWB  = ATT_STRIDE * 2;        // 272 B
constexpr int QTILE = 128 * ROWB;            // 34816
constexpr int KTILE = 64 * ROWB;             // 17408
constexpr int KVSTAGE = 2 * KTILE;           // 34816
constexpr int ATT_SMEM = 4 * KVSTAGE;        // 139264

__global__ __launch_bounds__(256)
void attn_mma(const __half* __restrict__ Qh, const __half* __restrict__ Ql,
              const __half* __restrict__ Kh, const __half* __restrict__ Vh,
              __half* __restrict__ ao2)
{
    extern __shared__ char sm[];
    const uint32_t sb = smem_u32(sm);

    const int qb = gridDim.x - 1 - blockIdx.x;
    const int h  = blockIdx.y;
    const int b  = blockIdx.z;
    const int kh = h >> 2;
    const int tid = threadIdx.x;
    const int wid = tid >> 5;
    const int lane = tid & 31;
    const int q0 = qb * 128;
    const int nkb = q0 / 64 + 2;

    const int grp = lane >> 3, lr = lane & 7;

    {
        const size_t qrow = ((size_t)(b * SEQ + q0) * NH + h) * HD;
        for (int i = tid; i < 2048; i += 256) {
            int r = i >> 4, ch = i & 15;
            size_t g = qrow + (size_t)r * NH * HD + ch * 8;
            uint32_t so = r * ROWB + ch * 16;
            cp16(sb + so, Qh + g);
            cp16(sb + QTILE + so, Ql + g);
        }
    }
    asm volatile("cp.async.commit_group;" ::: "memory");
    asm volatile("cp.async.wait_group 0;" ::: "memory");
    __syncthreads();

    uint32_t qh_r[8][4], ql_r[8][4];
    {
        const uint32_t qa_h = sb + (wid * 16 + (grp & 1) * 8 + lr) * ROWB
                            + (grp >> 1) * 16;
        const uint32_t qa_l = qa_h + QTILE;
        #pragma unroll
        for (int ks = 0; ks < 8; ks++) {
            ldsm_x4(qh_r[ks], qa_h + ks * 32);
            ldsm_x4(ql_r[ks], qa_l + ks * 32);
        }
    }
    __syncthreads();

    auto issue_kv = [&](int kb) {
        const uint32_t st = sb + (kb & 3) * KVSTAGE;
        const size_t kvrow = ((size_t)(b * SEQ + kb * 64) * NKV + kh) * HD;
        for (int i = tid; i < 1024; i += 256) {
            int r = i >> 4, ch = i & 15;
            size_t g = kvrow + (size_t)r * NKV * HD + ch * 8;
            uint32_t so = r * ROWB + ch * 16;
            cp16(st + so,         Kh + g);
            cp16(st + KTILE + so, Vh + g);
        }
    };

    #pragma unroll
    for (int p = 0; p < 3; p++) {
        if (p < nkb) issue_kv(p);
        asm volatile("cp.async.commit_group;" ::: "memory");
    }

    const uint32_t kboff = ((grp >> 1) * 8 + lr) * ROWB + (grp & 1) * 16;
    const uint32_t vboff = ((grp & 1) * 8 + lr) * ROWB + (grp >> 1) * 16;

    float m_[2] = {-1e30f, -1e30f};
    float l_[2] = {0.f, 0.f};
    float of[16][4];
    #pragma unroll
    for (int nf = 0; nf < 16; nf++)
        #pragma unroll
        for (int e = 0; e < 4; e++) of[nf][e] = 0.f;

    const float scale = 0.08838834764831845f;
    const int rbase = q0 + wid * 16 + (lane >> 2);

    for (int kb = 0; kb < nkb; kb++) {
        asm volatile("cp.async.wait_group 2;" ::: "memory");
        __syncthreads();
        if (kb + 3 < nkb) issue_kv(kb + 3);
        asm volatile("cp.async.commit_group;" ::: "memory");

        const uint32_t st = sb + (kb & 3) * KVSTAGE;

        float sf[8][4];
        #pragma unroll
        for (int f = 0; f < 8; f++)
            #pragma unroll
            for (int e = 0; e < 4; e++) sf[f][e] = 0.f;

        {
            uint32_t bh0[4], bh1[4];
            ldsm_x4(bh0, st + kboff);
            #pragma unroll
            for (int t = 0; t < 32; t++) {
                const int ks = t >> 2, nb = t & 3;
                uint32_t* cur = (t & 1) ? bh1 : bh0;
                uint32_t* nxt = (t & 1) ? bh0 : bh1;
                if (t + 1 < 32) {
                    const int ks2 = (t + 1) >> 2, nb2 = (t + 1) & 3;
                    ldsm_x4(nxt, st + kboff + nb2 * 16 * ROWB + ks2 * 32);
                }
                mma_f16(sf[2 * nb],     qh_r[ks], cur);
                mma_f16(sf[2 * nb + 1], qh_r[ks], cur + 2);
                mma_f16(sf[2 * nb],     ql_r[ks], cur);
                mma_f16(sf[2 * nb + 1], ql_r[ks], cur + 2);
            }
        }

        float mx[2] = {-1e30f, -1e30f};
        #pragma unroll
        for (int f = 0; f < 8; f++)
            #pragma unroll
            for (int e = 0; e < 4; e++) {
                float v = sf[f][e] * scale;
                int col = kb * 64 + f * 8 + ((lane & 3) << 1) + (e & 1);
                int row = rbase + ((e & 2) << 2);
                v = (col > row) ? -1e30f : v;
                sf[f][e] = v;
                mx[e >> 1] = fmaxf(mx[e >> 1], v);
            }
        #pragma unroll
        for (int e = 0; e < 2; e++) {
            mx[e] = fmaxf(mx[e], __shfl_xor_sync(0xffffffffu, mx[e], 1));
            mx[e] = fmaxf(mx[e], __shfl_xor_sync(0xffffffffu, mx[e], 2));
        }
        float mn[2], alp[2], rs[2] = {0.f, 0.f};
        #pragma unroll
        for (int e = 0; e < 2; e++) {
            mn[e]  = fmaxf(m_[e], mx[e]);
            alp[e] = __expf(m_[e] - mn[e]);
            m_[e]  = mn[e];
        }
        #pragma unroll
        for (int f = 0; f < 8; f++)
            #pragma unroll
            for (int e = 0; e < 4; e++) {
                float p = __expf(sf[f][e] - mn[e >> 1]);
                sf[f][e] = p;
                rs[e >> 1] += p;
            }
        #pragma unroll
        for (int e = 0; e < 2; e++) {
            rs[e] += __shfl_xor_sync(0xffffffffu, rs[e], 1);
            rs[e] += __shfl_xor_sync(0xffffffffu, rs[e], 2);
            l_[e] = l_[e] * alp[e] + rs[e];
        }
        #pragma unroll
        for (int nf = 0; nf < 16; nf++) {
            of[nf][0] *= alp[0]; of[nf][1] *= alp[0];
            of[nf][2] *= alp[1]; of[nf][3] *= alp[1];
        }

        {
            uint32_t PH[4][4], PL[4][4];
            #pragma unroll
            for (int ks = 0; ks < 4; ks++) {
                split2h(sf[2 * ks][0],     sf[2 * ks][1],     PH[ks][0], PL[ks][0]);
                split2h(sf[2 * ks][2],     sf[2 * ks][3],     PH[ks][1], PL[ks][1]);
                split2h(sf[2 * ks + 1][0], sf[2 * ks + 1][1], PH[ks][2], PL[ks][2]);
                split2h(sf[2 * ks + 1][2], sf[2 * ks + 1][3], PH[ks][3], PL[ks][3]);
            }
            uint32_t vv0[4], vv1[4];
            ldsm_x4_t(vv0, st + KTILE + vboff);
            #pragma unroll
            for (int t = 0; t < 32; t++) {
                const int ks = t >> 3, nb = t & 7;
                uint32_t* cur = (t & 1) ? vv1 : vv0;
                uint32_t* nxt = (t & 1) ? vv0 : vv1;
                if (t + 1 < 32) {
                    const int ks2 = (t + 1) >> 3, nb2 = (t + 1) & 7;
                    ldsm_x4_t(nxt, st + KTILE + vboff + ks2 * 16 * ROWB + nb2 * 32);
                }
                mma_f16(of[2 * nb],     PH[ks], cur);
                mma_f16(of[2 * nb + 1], PH[ks], cur + 2);
                mma_f16(of[2 * nb],     PL[ks], cur);
                mma_f16(of[2 * nb + 1], PL[ks], cur + 2);
            }
        }
    }

    float inv0 = 1.f / l_[0], inv1 = 1.f / l_[1];
    size_t b0 = (size_t)(b * SEQ + rbase) * K2 + h * HD + ((lane & 3) << 1);
    size_t b1 = b0 + (size_t)8 * K2;
    #pragma unroll
    for (int nf = 0; nf < 16; nf++) {
        uint32_t hi, lo;
        split2h(of[nf][0] * inv0, of[nf][1] * inv0, hi, lo);
        *(uint32_t*)(ao2 + b0 + nf * 8)          = hi;
        *(uint32_t*)(ao2 + b0 + DMODEL + nf * 8) = lo;
        split2h(of[nf][2] * inv1, of[nf][3] * inv1, hi, lo);
        *(uint32_t*)(ao2 + b1 + nf * 8)          = hi;
        *(uint32_t*)(ao2 + b1 + DMODEL + nf * 8) = lo;
    }
}

// ============================================================================
// host launcher
// ============================================================================
extern "C" void kernel_launch(void* const* d_in, const int* in_sizes, int n_in,
                              void* d_out, int out_size)
{
    const float* x  = (const float*)d_in[0];
    const float* fc = (const float*)d_in[1];
    const float* fs = (const float*)d_in[2];
    const float* wq = (const float*)d_in[4];
    const float* wk = (const float*)d_in[5];
    const float* wv = (const float*)d_in[6];
    const float* wo = (const float*)d_in[7];
    float* out = (float*)d_out;

    __half *x2, *ao2, *wqh, *wkh, *wvh, *woh, *qh2, *ql2, *kh2, *vh2;
    cudaGetSymbolAddress((void**)&x2,  g_x2);
    cudaGetSymbolAddress((void**)&ao2, g_ao2);
    cudaGetSymbolAddress((void**)&wqh, g_wqh);
    cudaGetSymbolAddress((void**)&wkh, g_wkh);
    cudaGetSymbolAddress((void**)&wvh, g_wvh);
    cudaGetSymbolAddress((void**)&woh, g_woh);
    cudaGetSymbolAddress((void**)&qh2, g_qh2);
    cudaGetSymbolAddress((void**)&ql2, g_ql2);
    cudaGetSymbolAddress((void**)&kh2, g_kh2);
    cudaGetSymbolAddress((void**)&vh2, g_vh2);

    cudaFuncSetAttribute(qkv_gemm, cudaFuncAttributeMaxDynamicSharedMemorySize,
                         GEMM16_SMEM);
    cudaFuncSetAttribute(wo_gemm, cudaFuncAttributeMaxDynamicSharedMemorySize,
                         GEMM16_SMEM);
    cudaFuncSetAttribute(attn_mma, cudaFuncAttributeMaxDynamicSharedMemorySize,
                         ATT_SMEM);

    // ---- single merged conversion launch ----
    convert_all<<<(unsigned)(CQ_WO / 256), 256>>>(
        (const float4*)x, (const float4*)wq, (const float4*)wk,
        (const float4*)wv, (const float4*)wo, x2, wqh, wkh, wvh, woh);

    // ---- fused QKV projection + RoPE + fp16 split ----
    qkv_gemm<<<dim3(24, MROWS / 128), 128, GEMM16_SMEM>>>(
        x2, wqh, wkh, wvh, fc, fs, qh2, ql2, kh2, vh2);

    // ---- tensor-core causal attention ----
    attn_mma<<<dim3(SEQ / 128, NH, BB), 256, ATT_SMEM>>>(qh2, ql2, kh2, vh2, ao2);

    // ---- output projection ----
    wo_gemm<<<dim3(DMODEL / 128, MROWS / 128), 128, GEMM16_SMEM>>>(ao2, woh, out);
}

// round 13
// speedup vs baseline: 1.0006x; 1.0006x over previous
#include <cuda_runtime.h>
#include <cuda_fp16.h>
#include <math.h>
#include <cstdint>

// ---------------- problem constants ----------------
constexpr int BB     = 2;
constexpr int SEQ    = 2048;
constexpr int DMODEL = 2048;
constexpr int NH     = 16;
constexpr int NKV    = 4;
constexpr int HD     = 128;
constexpr int MROWS  = BB * SEQ;     // 4096
constexpr int QE     = NH * HD;      // 2048
constexpr int KVE    = NKV * HD;     // 512
constexpr int K2     = 4096;         // x stored as [hi(2048) | lo(2048)]
constexpr int NCH    = 64;           // k-chunks of 32 over DMODEL

// ---------------- scratch ----------------
__device__ __half g_x2 [(size_t)MROWS * K2];    // [xh | xl]
__device__ __half g_ao2[(size_t)MROWS * K2];    // [aoh | aol]
__device__ __half g_wqh[(size_t)QE     * DMODEL];
__device__ __half g_wkh[(size_t)KVE    * DMODEL];
__device__ __half g_wvh[(size_t)KVE    * DMODEL];
__device__ __half g_woh[(size_t)DMODEL * DMODEL];

__device__ __half g_qh2[(size_t)MROWS * QE];
__device__ __half g_ql2[(size_t)MROWS * QE];
__device__ __half g_kh2[(size_t)MROWS * KVE];
__device__ __half g_vh2[(size_t)MROWS * KVE];

// ---------------- helpers ----------------
__device__ __forceinline__ uint32_t smem_u32(const void* p) {
    uint32_t a;
    asm("{ .reg .u64 t; cvta.to.shared.u64 t, %1; cvt.u32.u64 %0, t; }"
        : "=r"(a) : "l"(p));
    return a;
}
__device__ __forceinline__ void cp16(uint32_t dst, const void* src) {
    asm volatile("cp.async.cg.shared.global [%0], [%1], 16;"
                 :: "r"(dst), "l"(src));
}
__device__ __forceinline__ void ldsm_x4(uint32_t* r, uint32_t addr) {
    asm volatile("ldmatrix.sync.aligned.m8n8.x4.shared.b16 {%0,%1,%2,%3}, [%4];"
                 : "=r"(r[0]), "=r"(r[1]), "=r"(r[2]), "=r"(r[3]) : "r"(addr));
}
__device__ __forceinline__ void ldsm_x4_t(uint32_t* r, uint32_t addr) {
    asm volatile("ldmatrix.sync.aligned.m8n8.x4.trans.shared.b16 {%0,%1,%2,%3}, [%4];"
                 : "=r"(r[0]), "=r"(r[1]), "=r"(r[2]), "=r"(r[3]) : "r"(addr));
}
__device__ __forceinline__ void mma_f16(float* d, const uint32_t* a,
                                        const uint32_t* b) {
    asm volatile(
        "mma.sync.aligned.m16n8k16.row.col.f32.f16.f16.f32 "
        "{%0,%1,%2,%3}, {%4,%5,%6,%7}, {%8,%9}, {%0,%1,%2,%3};"
        : "+f"(d[0]), "+f"(d[1]), "+f"(d[2]), "+f"(d[3])
        : "r"(a[0]), "r"(a[1]), "r"(a[2]), "r"(a[3]), "r"(b[0]), "r"(b[1]));
}
__device__ __forceinline__ uint32_t pack_f16(float lo, float hi) {
    uint32_t r;
    asm("cvt.rn.f16x2.f32 %0, %1, %2;" : "=r"(r) : "f"(hi), "f"(lo));
    return r;
}
__device__ __forceinline__ void split2h(float x, float y, uint32_t& hi, uint32_t& lo) {
    uint32_t h = pack_f16(x, y);
    __half2 hb = *reinterpret_cast<__half2*>(&h);
    lo = pack_f16(x - __half2float(hb.x), y - __half2float(hb.y));
    hi = h;
}

// ============================================================================
// merged conversion kernel
// ============================================================================
constexpr size_t CQ_X  = 2097152;
constexpr size_t CQ_WQ = CQ_X  + 1048576;
constexpr size_t CQ_WK = CQ_WQ + 262144;
constexpr size_t CQ_WV = CQ_WK + 262144;
constexpr size_t CQ_WO = CQ_WV + 1048576;

__global__ __launch_bounds__(256)
void convert_all(const float4* __restrict__ x,  const float4* __restrict__ wq,
                 const float4* __restrict__ wk, const float4* __restrict__ wv,
                 const float4* __restrict__ wo,
                 __half* __restrict__ x2,  __half* __restrict__ wqh,
                 __half* __restrict__ wkh, __half* __restrict__ wvh,
                 __half* __restrict__ woh)
{
    size_t i = (size_t)blockIdx.x * 256 + threadIdx.x;
    if (i < CQ_X) {
        float4 v = x[i];
        size_t e = i * 4;
        size_t r = e >> 11;
        int    c = (int)(e & 2047);
        float xs[4] = {v.x, v.y, v.z, v.w};
        __half* d = x2 + r * (size_t)K2 + c;
        #pragma unroll
        for (int j = 0; j < 4; j++) {
            __half h = __float2half(xs[j]);
            d[j]          = h;
            d[DMODEL + j] = __float2half(xs[j] - __half2float(h));
        }
        return;
    }
    const float4* src; __half* dst; size_t j;
    if      (i < CQ_WQ) { src = wq; dst = wqh; j = i - CQ_X;  }
    else if (i < CQ_WK) { src = wk; dst = wkh; j = i - CQ_WQ; }
    else if (i < CQ_WV) { src = wv; dst = wvh; j = i - CQ_WK; }
    else                { src = wo; dst = woh; j = i - CQ_WV; }
    float4 v = src[j];
    size_t e = j * 4;
    dst[e]     = __float2half(v.x);
    dst[e + 1] = __float2half(v.y);
    dst[e + 2] = __float2half(v.z);
    dst[e + 3] = __float2half(v.w);
}

// ============================================================================
// GEMM config — hi/lo-fused chunks, B loaded once per k.
// MMA issue order: all ah-MMAs first, then all al-MMAs (no same-acc
// back-to-back dependency — the R12 regression).
// ============================================================================
constexpr int HROWB  = 80;                 // bytes per smem row (40 halves)
constexpr int GTILE  = 128 * HROWB;        // 10240 B
constexpr int GSTAGE = 3 * GTILE;          // Ah + Al + B   = 30720 B
constexpr int GEMM16_SMEM = 3 * GSTAGE;    // 3 stages      = 92160 B

template <typename EPI>
__device__ __forceinline__
void gemm16_body(const __half* __restrict__ A, const __half* __restrict__ Bw,
                 int m0, int n0loc, EPI epi)
{
    extern __shared__ char sm[];
    const uint32_t sb = smem_u32(sm);
    const int tid = threadIdx.x;
    const int wid = tid >> 5;
    const int lane = tid & 31;
    const int wm = (wid >> 1) * 64;    // warp m offset (0/64)
    const int wn = (wid & 1) * 64;     // warp n offset (0/64)

    const __half* Abase = A  + (size_t)m0 * K2;
    const __half* Bbase = Bw + (size_t)n0loc * DMODEL;

    const int grp = lane >> 3, lr = lane & 7;
    const uint32_t aoff0 = (wm + (grp & 1) * 8 + lr) * HROWB + (grp >> 1) * 16;
    const uint32_t boff0 = 2 * GTILE + (wn + (grp >> 1) * 8 + lr) * HROWB
                         + (grp & 1) * 16;

    float acc[4][8][4];
    #pragma unroll
    for (int mf = 0; mf < 4; mf++)
        #pragma unroll
        for (int nf = 0; nf < 8; nf++)
            #pragma unroll
            for (int e = 0; e < 4; e++) acc[mf][nf][e] = 0.f;

    auto issue = [&](int c) {
        if (c >= NCH) return;
        const uint32_t st = sb + (c % 3) * GSTAGE;
        const __half* Ah = Abase + c * 32;             // hi half
        const __half* Al = Abase + DMODEL + c * 32;    // lo half
        const __half* Bg = Bbase + c * 32;
        #pragma unroll
        for (int t = 0; t < 4; t++) {
            int i = tid + t * 128;
            int row = i >> 2, seg = i & 3;
            cp16(st + row * HROWB + seg * 16,
                 Ah + (size_t)row * K2 + seg * 8);
            cp16(st + GTILE + row * HROWB + seg * 16,
                 Al + (size_t)row * K2 + seg * 8);
            cp16(st + 2 * GTILE + row * HROWB + seg * 16,
                 Bg + (size_t)row * DMODEL + seg * 8);
        }
    };

    issue(0); asm volatile("cp.async.commit_group;" ::: "memory");
    issue(1); asm volatile("cp.async.commit_group;" ::: "memory");

    uint32_t ah[4][4], al[4][4], br[4][4];

    for (int c = 0; c < NCH; c++) {
        asm volatile("cp.async.wait_group 1;" ::: "memory"); // stage c done
        __syncthreads();        // stage c visible to all; stage c-1 fully read
        issue(c + 2);           // overwrite stage (c-1)%3 (safe per barrier)
        asm volatile("cp.async.commit_group;" ::: "memory");

        const uint32_t st = sb + (c % 3) * GSTAGE;
        #pragma unroll
        for (int s = 0; s < 2; s++) {
            const uint32_t koff = s * 32;
            #pragma unroll
            for (int mf = 0; mf < 4; mf++) {
                ldsm_x4(ah[mf], st + aoff0 + mf * (16 * HROWB) + koff);
                ldsm_x4(al[mf], st + GTILE + aoff0 + mf * (16 * HROWB) + koff);
            }
            #pragma unroll
            for (int nf2 = 0; nf2 < 4; nf2++)
                ldsm_x4(br[nf2], st + boff0 + nf2 * (16 * HROWB) + koff);
            // pass 1: all hi-MMAs (32 independent)
            #pragma unroll
            for (int mf = 0; mf < 4; mf++)
                #pragma unroll
                for (int nf = 0; nf < 8; nf++)
                    mma_f16(acc[mf][nf], ah[mf], &br[nf >> 1][(nf & 1) * 2]);
            // pass 2: all lo-MMAs (each acc's 2nd update 31 MMAs later)
            #pragma unroll
            for (int mf = 0; mf < 4; mf++)
                #pragma unroll
                for (int nf = 0; nf < 8; nf++)
                    mma_f16(acc[mf][nf], al[mf], &br[nf >> 1][(nf & 1) * 2]);
        }
    }

    const int lr4 = lane >> 2, lc2 = (lane & 3) * 2;
    #pragma unroll
    for (int mf = 0; mf < 4; mf++) {
        int r = m0 + wm + mf * 16 + lr4;
        #pragma unroll
        for (int nf = 0; nf < 8; nf++) {
            int cc = wn + nf * 8 + lc2;
            epi(r,     cc, acc[mf][nf][0], acc[mf][nf][1]);
            epi(r + 8, cc, acc[mf][nf][2], acc[mf][nf][3]);
        }
    }
}

// ============================================================================
// fused QKV projection (epilogue: RoPE + fp16 split)
// ============================================================================
__global__ __launch_bounds__(128, 2)
void qkv_gemm(const __half* __restrict__ x2,
              const __half* __restrict__ wqh, const __half* __restrict__ wkh,
              const __half* __restrict__ wvh,
              const float* __restrict__ fc, const float* __restrict__ fs,
              __half* __restrict__ qh2, __half* __restrict__ ql2,
              __half* __restrict__ kh2, __half* __restrict__ vh2)
{
    const int bx = blockIdx.x;
    const int m0 = blockIdx.y * 128;

    if (bx < 16) {
        const int n0 = bx * 128;
        gemm16_body(x2, wqh, m0, n0,
            [&](int r, int cc, float e, float o) {
                int col = n0 + cc;
                int s = r & (SEQ - 1);
                int p = (col & 127) >> 1;
                float c  = fc[s * 64 + p];
                float si = fs[s * 64 + p];
                float re = e * c - o * si;
                float ro = e * si + o * c;
                uint32_t hi, lo;
                split2h(re, ro, hi, lo);
                size_t idx = (size_t)r * QE + col;
                *(uint32_t*)(qh2 + idx) = hi;
                *(uint32_t*)(ql2 + idx) = lo;
            });
    } else if (bx < 20) {
        const int n0 = (bx - 16) * 128;
        gemm16_body(x2, wkh, m0, n0,
            [&](int r, int cc, float e, float o) {
                int col = n0 + cc;
                int s = r & (SEQ - 1);
                int p = (col & 127) >> 1;
                float c  = fc[s * 64 + p];
                float si = fs[s * 64 + p];
                float re = e * c - o * si;
                float ro = e * si + o * c;
                *(uint32_t*)(kh2 + (size_t)r * KVE + col) = pack_f16(re, ro);
            });
    } else {
        const int n0 = (bx - 20) * 128;
        gemm16_body(x2, wvh, m0, n0,
            [&](int r, int cc, float e, float o) {
                *(uint32_t*)(vh2 + (size_t)r * KVE + n0 + cc) = pack_f16(e, o);
            });
    }
}

// ============================================================================
// output projection
// ============================================================================
__global__ __launch_bounds__(128, 2)
void wo_gemm(const __half* __restrict__ ao2, const __half* __restrict__ woh,
             float* __restrict__ out)
{
    const int n0 = blockIdx.x * 128;
    const int m0 = blockIdx.y * 128;
    gemm16_body(ao2, woh, m0, n0,
        [&](int r, int cc, float e, float o) {
            *(float2*)(out + (size_t)r * DMODEL + n0 + cc) = make_float2(e, o);
        });
}

// ============================================================================
// fp16 2-term tensor-core causal flash attention (Br=128, Bc=64)
// (unchanged from R11/R12 passing versions)
// ============================================================================
constexpr int ATT_STRIDE = 136;
constexpr int ROWB  = ATT_STRIDE * 2;        // 272 B
constexpr int QTILE = 128 * ROWB;            // 34816
constexpr int KTILE = 64 * ROWB;             // 17408
constexpr int KVSTAGE = 2 * KTILE;           // 34816
constexpr int ATT_SMEM = 4 * KVSTAGE;        // 139264

__global__ __launch_bounds__(256)
void attn_mma(const __half* __restrict__ Qh, const __half* __restrict__ Ql,
              const __half* __restrict__ Kh, const __half* __restrict__ Vh,
              __half* __restrict__ ao2)
{
    extern __shared__ char sm[];
    const uint32_t sb = smem_u32(sm);

    const int qb = gridDim.x - 1 - blockIdx.x;
    const int h  = blockIdx.y;
    const int b  = blockIdx.z;
    const int kh = h >> 2;
    const int tid = threadIdx.x;
    const int wid = tid >> 5;
    const int lane = tid & 31;
    const int q0 = qb * 128;
    const int nkb = q0 / 64 + 2;

    const int grp = lane >> 3, lr = lane & 7;

    {
        const size_t qrow = ((size_t)(b * SEQ + q0) * NH + h) * HD;
        for (int i = tid; i < 2048; i += 256) {
            int r = i >> 4, ch = i & 15;
            size_t g = qrow + (size_t)r * NH * HD + ch * 8;
            uint32_t so = r * ROWB + ch * 16;
            cp16(sb + so, Qh + g);
            cp16(sb + QTILE + so, Ql + g);
        }
    }
    asm volatile("cp.async.commit_group;" ::: "memory");
    asm volatile("cp.async.wait_group 0;" ::: "memory");
    __syncthreads();

    uint32_t qh_r[8][4], ql_r[8][4];
    {
        const uint32_t qa_h = sb + (wid * 16 + (grp & 1) * 8 + lr) * ROWB
                            + (grp >> 1) * 16;
        const uint32_t qa_l = qa_h + QTILE;
        #pragma unroll
        for (int ks = 0; ks < 8; ks++) {
            ldsm_x4(qh_r[ks], qa_h + ks * 32);
            ldsm_x4(ql_r[ks], qa_l + ks * 32);
        }
    }
    __syncthreads();

    auto issue_kv = [&](int kb) {
        const uint32_t st = sb + (kb & 3) * KVSTAGE;
        const size_t kvrow = ((size_t)(b * SEQ + kb * 64) * NKV + kh) * HD;
        for (int i = tid; i < 1024; i += 256) {
            int r = i >> 4, ch = i & 15;
            size_t g = kvrow + (size_t)r * NKV * HD + ch * 8;
            uint32_t so = r * ROWB + ch * 16;
            cp16(st + so,         Kh + g);
            cp16(st + KTILE + so, Vh + g);
        }
    };

    #pragma unroll
    for (int p = 0; p < 3; p++) {
        if (p < nkb) issue_kv(p);
        asm volatile("cp.async.commit_group;" ::: "memory");
    }

    const uint32_t kboff = ((grp >> 1) * 8 + lr) * ROWB + (grp & 1) * 16;
    const uint32_t vboff = ((grp & 1) * 8 + lr) * ROWB + (grp >> 1) * 16;

    float m_[2] = {-1e30f, -1e30f};
    float l_[2] = {0.f, 0.f};
    float of[16][4];
    #pragma unroll
    for (int nf = 0; nf < 16; nf++)
        #pragma unroll
        for (int e = 0; e < 4; e++) of[nf][e] = 0.f;

    const float scale = 0.08838834764831845f;
    const int rbase = q0 + wid * 16 + (lane >> 2);

    for (int kb = 0; kb < nkb; kb++) {
        asm volatile("cp.async.wait_group 2;" ::: "memory");
        __syncthreads();
        if (kb + 3 < nkb) issue_kv(kb + 3);
        asm volatile("cp.async.commit_group;" ::: "memory");

        const uint32_t st = sb + (kb & 3) * KVSTAGE;

        float sf[8][4];
        #pragma unroll
        for (int f = 0; f < 8; f++)
            #pragma unroll
            for (int e = 0; e < 4; e++) sf[f][e] = 0.f;

        {
            uint32_t bh0[4], bh1[4];
            ldsm_x4(bh0, st + kboff);
            #pragma unroll
            for (int t = 0; t < 32; t++) {
                const int ks = t >> 2, nb = t & 3;
                uint32_t* cur = (t & 1) ? bh1 : bh0;
                uint32_t* nxt = (t & 1) ? bh0 : bh1;
                if (t + 1 < 32) {
                    const int ks2 = (t + 1) >> 2, nb2 = (t + 1) & 3;
                    ldsm_x4(nxt, st + kboff + nb2 * 16 * ROWB + ks2 * 32);
                }
                mma_f16(sf[2 * nb],     qh_r[ks], cur);
                mma_f16(sf[2 * nb + 1], qh_r[ks], cur + 2);
                mma_f16(sf[2 * nb],     ql_r[ks], cur);
                mma_f16(sf[2 * nb + 1], ql_r[ks], cur + 2);
            }
        }

        float mx[2] = {-1e30f, -1e30f};
        #pragma unroll
        for (int f = 0; f < 8; f++)
            #pragma unroll
            for (int e = 0; e < 4; e++) {
                float v = sf[f][e] * scale;
                int col = kb * 64 + f * 8 + ((lane & 3) << 1) + (e & 1);
                int row = rbase + ((e & 2) << 2);
                v = (col > row) ? -1e30f : v;
                sf[f][e] = v;
                mx[e >> 1] = fmaxf(mx[e >> 1], v);
            }
        #pragma unroll
        for (int e = 0; e < 2; e++) {
            mx[e] = fmaxf(mx[e], __shfl_xor_sync(0xffffffffu, mx[e], 1));
            mx[e] = fmaxf(mx[e], __shfl_xor_sync(0xffffffffu, mx[e], 2));
        }
        float mn[2], alp[2], rs[2] = {0.f, 0.f};
        #pragma unroll
        for (int e = 0; e < 2; e++) {
            mn[e]  = fmaxf(m_[e], mx[e]);
            alp[e] = __expf(m_[e] - mn[e]);
            m_[e]  = mn[e];
        }
        #pragma unroll
        for (int f = 0; f < 8; f++)
            #pragma unroll
            for (int e = 0; e < 4; e++) {
                float p = __expf(sf[f][e] - mn[e >> 1]);
                sf[f][e] = p;
                rs[e >> 1] += p;
            }
        #pragma unroll
        for (int e = 0; e < 2; e++) {
            rs[e] += __shfl_xor_sync(0xffffffffu, rs[e], 1);
            rs[e] += __shfl_xor_sync(0xffffffffu, rs[e], 2);
            l_[e] = l_[e] * alp[e] + rs[e];
        }
        #pragma unroll
        for (int nf = 0; nf < 16; nf++) {
            of[nf][0] *= alp[0]; of[nf][1] *= alp[0];
            of[nf][2] *= alp[1]; of[nf][3] *= alp[1];
        }

        {
            uint32_t PH[4][4], PL[4][4];
            #pragma unroll
            for (int ks = 0; ks < 4; ks++) {
                split2h(sf[2 * ks][0],     sf[2 * ks][1],     PH[ks][0], PL[ks][0]);
                split2h(sf[2 * ks][2],     sf[2 * ks][3],     PH[ks][1], PL[ks][1]);
                split2h(sf[2 * ks + 1][0], sf[2 * ks + 1][1], PH[ks][2], PL[ks][2]);
                split2h(sf[2 * ks + 1][2], sf[2 * ks + 1][3], PH[ks][3], PL[ks][3]);
            }
            uint32_t vv0[4], vv1[4];
            ldsm_x4_t(vv0, st + KTILE + vboff);
            #pragma unroll
            for (int t = 0; t < 32; t++) {
                const int ks = t >> 3, nb = t & 7;
                uint32_t* cur = (t & 1) ? vv1 : vv0;
                uint32_t* nxt = (t & 1) ? vv0 : vv1;
                if (t + 1 < 32) {
                    const int ks2 = (t + 1) >> 3, nb2 = (t + 1) & 7;
                    ldsm_x4_t(nxt, st + KTILE + vboff + ks2 * 16 * ROWB + nb2 * 32);
                }
                mma_f16(of[2 * nb],     PH[ks], cur);
                mma_f16(of[2 * nb + 1], PH[ks], cur + 2);
                mma_f16(of[2 * nb],     PL[ks], cur);
                mma_f16(of[2 * nb + 1], PL[ks], cur + 2);
            }
        }
    }

    float inv0 = 1.f / l_[0], inv1 = 1.f / l_[1];
    size_t b0 = (size_t)(b * SEQ + rbase) * K2 + h * HD + ((lane & 3) << 1);
    size_t b1 = b0 + (size_t)8 * K2;
    #pragma unroll
    for (int nf = 0; nf < 16; nf++) {
        uint32_t hi, lo;
        split2h(of[nf][0] * inv0, of[nf][1] * inv0, hi, lo);
        *(uint32_t*)(ao2 + b0 + nf * 8)          = hi;
        *(uint32_t*)(ao2 + b0 + DMODEL + nf * 8) = lo;
        split2h(of[nf][2] * inv1, of[nf][3] * inv1, hi, lo);
        *(uint32_t*)(ao2 + b1 + nf * 8)          = hi;
        *(uint32_t*)(ao2 + b1 + DMODEL + nf * 8) = lo;
    }
}

// ============================================================================
// host launcher
// ============================================================================
extern "C" void kernel_launch(void* const* d_in, const int* in_sizes, int n_in,
                              void* d_out, int out_size)
{
    const float* x  = (const float*)d_in[0];
    const float* fc = (const float*)d_in[1];
    const float* fs = (const float*)d_in[2];
    const float* wq = (const float*)d_in[4];
    const float* wk = (const float*)d_in[5];
    const float* wv = (const float*)d_in[6];
    const float* wo = (const float*)d_in[7];
    float* out = (float*)d_out;

    __half *x2, *ao2, *wqh, *wkh, *wvh, *woh, *qh2, *ql2, *kh2, *vh2;
    cudaGetSymbolAddress((void**)&x2,  g_x2);
    cudaGetSymbolAddress((void**)&ao2, g_ao2);
    cudaGetSymbolAddress((void**)&wqh, g_wqh);
    cudaGetSymbolAddress((void**)&wkh, g_wkh);
    cudaGetSymbolAddress((void**)&wvh, g_wvh);
    cudaGetSymbolAddress((void**)&woh, g_woh);
    cudaGetSymbolAddress((void**)&qh2, g_qh2);
    cudaGetSymbolAddress((void**)&ql2, g_ql2);
    cudaGetSymbolAddress((void**)&kh2, g_kh2);
    cudaGetSymbolAddress((void**)&vh2, g_vh2);

    cudaFuncSetAttribute(qkv_gemm, cudaFuncAttributeMaxDynamicSharedMemorySize,
                         GEMM16_SMEM);
    cudaFuncSetAttribute(wo_gemm, cudaFuncAttributeMaxDynamicSharedMemorySize,
                         GEMM16_SMEM);
    cudaFuncSetAttribute(attn_mma, cudaFuncAttributeMaxDynamicSharedMemorySize,
                         ATT_SMEM);

    // ---- single merged conversion launch ----
    convert_all<<<(unsigned)(CQ_WO / 256), 256>>>(
        (const float4*)x, (const float4*)wq, (const float4*)wk,
        (const float4*)wv, (const float4*)wo, x2, wqh, wkh, wvh, woh);

    // ---- fused QKV projection + RoPE + fp16 split ----
    qkv_gemm<<<dim3(24, MROWS / 128), 128, GEMM16_SMEM>>>(
        x2, wqh, wkh, wvh, fc, fs, qh2, ql2, kh2, vh2);

    // ---- tensor-core causal attention ----
    attn_mma<<<dim3(SEQ / 128, NH, BB), 256, ATT_SMEM>>>(qh2, ql2, kh2, vh2, ao2);

    // ---- output projection ----
    wo_gemm<<<dim3(DMODEL / 128, MROWS / 128), 128, GEMM16_SMEM>>>(ao2, woh, out);
}

// round 14
// speedup vs baseline: 1.1002x; 1.0995x over previous
#include <cuda_runtime.h>
#include <cuda_fp16.h>
#include <math.h>
#include <cstdint>

// ---------------- problem constants ----------------
constexpr int BB     = 2;
constexpr int SEQ    = 2048;
constexpr int DMODEL = 2048;
constexpr int NH     = 16;
constexpr int NKV    = 4;
constexpr int HD     = 128;
constexpr int MROWS  = BB * SEQ;     // 4096
constexpr int QE     = NH * HD;      // 2048
constexpr int KVE    = NKV * HD;     // 512
constexpr int K2     = 4096;         // 2-term fp16 split K
constexpr int NCH2   = 128;          // chunks of 32 over K2

// ---------------- scratch ----------------
__device__ __half g_x2 [(size_t)MROWS * K2];    // [xh | xl]
__device__ __half g_ao2[(size_t)MROWS * K2];    // [aoh | aol]
__device__ __half g_wqh[(size_t)QE     * DMODEL];
__device__ __half g_wkh[(size_t)KVE    * DMODEL];
__device__ __half g_wvh[(size_t)KVE    * DMODEL];
__device__ __half g_woh[(size_t)DMODEL * DMODEL];

__device__ __half g_qh2[(size_t)MROWS * QE];
__device__ __half g_ql2[(size_t)MROWS * QE];
__device__ __half g_kh2[(size_t)MROWS * KVE];
__device__ __half g_vh2[(size_t)MROWS * KVE];

// ---------------- helpers ----------------
__device__ __forceinline__ uint32_t smem_u32(const void* p) {
    uint32_t a;
    asm("{ .reg .u64 t; cvta.to.shared.u64 t, %1; cvt.u32.u64 %0, t; }"
        : "=r"(a) : "l"(p));
    return a;
}
__device__ __forceinline__ void cp16(uint32_t dst, const void* src) {
    asm volatile("cp.async.cg.shared.global [%0], [%1], 16;"
                 :: "r"(dst), "l"(src));
}
__device__ __forceinline__ void ldsm_x4(uint32_t* r, uint32_t addr) {
    asm volatile("ldmatrix.sync.aligned.m8n8.x4.shared.b16 {%0,%1,%2,%3}, [%4];"
                 : "=r"(r[0]), "=r"(r[1]), "=r"(r[2]), "=r"(r[3]) : "r"(addr));
}
__device__ __forceinline__ void ldsm_x4_t(uint32_t* r, uint32_t addr) {
    asm volatile("ldmatrix.sync.aligned.m8n8.x4.trans.shared.b16 {%0,%1,%2,%3}, [%4];"
                 : "=r"(r[0]), "=r"(r[1]), "=r"(r[2]), "=r"(r[3]) : "r"(addr));
}
__device__ __forceinline__ void mma_f16(float* d, const uint32_t* a,
                                        const uint32_t* b) {
    asm volatile(
        "mma.sync.aligned.m16n8k16.row.col.f32.f16.f16.f32 "
        "{%0,%1,%2,%3}, {%4,%5,%6,%7}, {%8,%9}, {%0,%1,%2,%3};"
        : "+f"(d[0]), "+f"(d[1]), "+f"(d[2]), "+f"(d[3])
        : "r"(a[0]), "r"(a[1]), "r"(a[2]), "r"(a[3]), "r"(b[0]), "r"(b[1]));
}
__device__ __forceinline__ uint32_t pack_f16(float lo, float hi) {
    uint32_t r;
    asm("cvt.rn.f16x2.f32 %0, %1, %2;" : "=r"(r) : "f"(hi), "f"(lo));
    return r;
}
__device__ __forceinline__ void split2h(float x, float y, uint32_t& hi, uint32_t& lo) {
    uint32_t h = pack_f16(x, y);
    __half2 hb = *reinterpret_cast<__half2*>(&h);
    lo = pack_f16(x - __half2float(hb.x), y - __half2float(hb.y));
    hi = h;
}

// ============================================================================
// merged conversion kernel
// ============================================================================
constexpr size_t CQ_X  = 2097152;
constexpr size_t CQ_WQ = CQ_X  + 1048576;
constexpr size_t CQ_WK = CQ_WQ + 262144;
constexpr size_t CQ_WV = CQ_WK + 262144;
constexpr size_t CQ_WO = CQ_WV + 1048576;

__global__ __launch_bounds__(256)
void convert_all(const float4* __restrict__ x,  const float4* __restrict__ wq,
                 const float4* __restrict__ wk, const float4* __restrict__ wv,
                 const float4* __restrict__ wo,
                 __half* __restrict__ x2,  __half* __restrict__ wqh,
                 __half* __restrict__ wkh, __half* __restrict__ wvh,
                 __half* __restrict__ woh)
{
    size_t i = (size_t)blockIdx.x * 256 + threadIdx.x;
    if (i < CQ_X) {
        float4 v = x[i];
        size_t e = i * 4;
        size_t r = e >> 11;
        int    c = (int)(e & 2047);
        float xs[4] = {v.x, v.y, v.z, v.w};
        __half* d = x2 + r * (size_t)K2 + c;
        #pragma unroll
        for (int j = 0; j < 4; j++) {
            __half h = __float2half(xs[j]);
            d[j]          = h;
            d[DMODEL + j] = __float2half(xs[j] - __half2float(h));
        }
        return;
    }
    const float4* src; __half* dst; size_t j;
    if      (i < CQ_WQ) { src = wq; dst = wqh; j = i - CQ_X;  }
    else if (i < CQ_WK) { src = wk; dst = wkh; j = i - CQ_WQ; }
    else if (i < CQ_WV) { src = wv; dst = wvh; j = i - CQ_WK; }
    else                { src = wo; dst = woh; j = i - CQ_WV; }
    float4 v = src[j];
    size_t e = j * 4;
    dst[e]     = __float2half(v.x);
    dst[e + 1] = __float2half(v.y);
    dst[e + 2] = __float2half(v.z);
    dst[e + 3] = __float2half(v.w);
}

// ============================================================================
// GEMM — R11 configuration (proven 744us): 4 warps, 64x64 warp tiles,
// BK=32 over K2=4096, 4-stage {A,B} ring, wait->barrier->issue ordering.
// NEW: section-1 fragment loads interleaved into section-0's MMA stream
// (intra-chunk, intra-stage: all between the same two barriers — race-free).
// ============================================================================
constexpr int HROWB  = 80;                 // bytes per smem row (40 halves)
constexpr int GTILE  = 128 * HROWB;        // 10240 B
constexpr int GSTAGE = 2 * GTILE;          // A + B
constexpr int GEMM16_SMEM = 4 * GSTAGE;    // 81920

template <typename EPI>
__device__ __forceinline__
void gemm16_body(const __half* __restrict__ A, const __half* __restrict__ Bw,
                 int m0, int n0loc, EPI epi)
{
    extern __shared__ char sm[];
    const uint32_t sb = smem_u32(sm);
    const int tid = threadIdx.x;
    const int wid = tid >> 5;
    const int lane = tid & 31;
    const int wm = (wid >> 1) * 64;    // warp m offset (0/64)
    const int wn = (wid & 1) * 64;     // warp n offset (0/64)

    const __half* Abase = A  + (size_t)m0 * K2;
    const __half* Bbase = Bw + (size_t)n0loc * DMODEL;

    const int grp = lane >> 3, lr = lane & 7;
    const uint32_t aoff0 = (wm + (grp & 1) * 8 + lr) * HROWB + (grp >> 1) * 16;
    const uint32_t boff0 = GTILE + (wn + (grp >> 1) * 8 + lr) * HROWB
                         + (grp & 1) * 16;

    float acc[4][8][4];
    #pragma unroll
    for (int mf = 0; mf < 4; mf++)
        #pragma unroll
        for (int nf = 0; nf < 8; nf++)
            #pragma unroll
            for (int e = 0; e < 4; e++) acc[mf][nf][e] = 0.f;

    auto issue = [&](int c) {
        if (c >= NCH2) return;
        const uint32_t st = sb + (c & 3) * GSTAGE;
        const __half* Ag = Abase + c * 32;
        const __half* Bg = Bbase + (c & 63) * 32;
        #pragma unroll
        for (int t = 0; t < 4; t++) {
            int i = tid + t * 128;
            int row = i >> 2, seg = i & 3;
            cp16(st + row * HROWB + seg * 16, Ag + (size_t)row * K2 + seg * 8);
        }
        #pragma unroll
        for (int t = 0; t < 4; t++) {
            int i = tid + t * 128;
            int row = i >> 2, seg = i & 3;
            cp16(st + GTILE + row * HROWB + seg * 16,
                 Bg + (size_t)row * DMODEL + seg * 8);
        }
    };

    issue(0); asm volatile("cp.async.commit_group;" ::: "memory");
    issue(1); asm volatile("cp.async.commit_group;" ::: "memory");
    issue(2); asm volatile("cp.async.commit_group;" ::: "memory");

    uint32_t arA[4][4], brA[4][4], arB[4][4], brB[4][4];

    for (int c = 0; c < NCH2; c++) {
        asm volatile("cp.async.wait_group 2;" ::: "memory"); // own copies of stage c done
        __syncthreads();        // stage c fully visible; stage c-1 fully consumed
        issue(c + 3);           // overwrite stage (c-1)&3
        asm volatile("cp.async.commit_group;" ::: "memory");

        const uint32_t st = sb + (c & 3) * GSTAGE;

        // section 0 fragment loads
        #pragma unroll
        for (int mf = 0; mf < 4; mf++)
            ldsm_x4(arA[mf], st + aoff0 + mf * (16 * HROWB));
        #pragma unroll
        for (int nf2 = 0; nf2 < 4; nf2++)
            ldsm_x4(brA[nf2], st + boff0 + nf2 * (16 * HROWB));

        // section 0 MMAs with section 1 loads interleaved (1 ldsm per 4 MMAs)
        #pragma unroll
        for (int mf = 0; mf < 4; mf++) {
            ldsm_x4(arB[mf], st + aoff0 + mf * (16 * HROWB) + 32);
            #pragma unroll
            for (int nf = 0; nf < 4; nf++)
                mma_f16(acc[mf][nf], arA[mf], &brA[nf >> 1][(nf & 1) * 2]);
            ldsm_x4(brB[mf], st + boff0 + mf * (16 * HROWB) + 32);
            #pragma unroll
            for (int nf = 4; nf < 8; nf++)
                mma_f16(acc[mf][nf], arA[mf], &brA[nf >> 1][(nf & 1) * 2]);
        }

        // section 1 MMAs
        #pragma unroll
        for (int mf = 0; mf < 4; mf++)
            #pragma unroll
            for (int nf = 0; nf < 8; nf++)
                mma_f16(acc[mf][nf], arB[mf], &brB[nf >> 1][(nf & 1) * 2]);
    }

    const int lr4 = lane >> 2, lc2 = (lane & 3) * 2;
    #pragma unroll
    for (int mf = 0; mf < 4; mf++) {
        int r = m0 + wm + mf * 16 + lr4;
        #pragma unroll
        for (int nf = 0; nf < 8; nf++) {
            int cc = wn + nf * 8 + lc2;
            epi(r,     cc, acc[mf][nf][0], acc[mf][nf][1]);
            epi(r + 8, cc, acc[mf][nf][2], acc[mf][nf][3]);
        }
    }
}

// ============================================================================
// fused QKV projection (epilogue: RoPE + fp16 split)
// ============================================================================
__global__ __launch_bounds__(128, 2)
void qkv_gemm(const __half* __restrict__ x2,
              const __half* __restrict__ wqh, const __half* __restrict__ wkh,
              const __half* __restrict__ wvh,
              const float* __restrict__ fc, const float* __restrict__ fs,
              __half* __restrict__ qh2, __half* __restrict__ ql2,
              __half* __restrict__ kh2, __half* __restrict__ vh2)
{
    const int bx = blockIdx.x;
    const int m0 = blockIdx.y * 128;

    if (bx < 16) {
        const int n0 = bx * 128;
        gemm16_body(x2, wqh, m0, n0,
            [&](int r, int cc, float e, float o) {
                int col = n0 + cc;
                int s = r & (SEQ - 1);
                int p = (col & 127) >> 1;
                float c  = fc[s * 64 + p];
                float si = fs[s * 64 + p];
                float re = e * c - o * si;
                float ro = e * si + o * c;
                uint32_t hi, lo;
                split2h(re, ro, hi, lo);
                size_t idx = (size_t)r * QE + col;
                *(uint32_t*)(qh2 + idx) = hi;
                *(uint32_t*)(ql2 + idx) = lo;
            });
    } else if (bx < 20) {
        const int n0 = (bx - 16) * 128;
        gemm16_body(x2, wkh, m0, n0,
            [&](int r, int cc, float e, float o) {
                int col = n0 + cc;
                int s = r & (SEQ - 1);
                int p = (col & 127) >> 1;
                float c  = fc[s * 64 + p];
                float si = fs[s * 64 + p];
                float re = e * c - o * si;
                float ro = e * si + o * c;
                *(uint32_t*)(kh2 + (size_t)r * KVE + col) = pack_f16(re, ro);
            });
    } else {
        const int n0 = (bx - 20) * 128;
        gemm16_body(x2, wvh, m0, n0,
            [&](int r, int cc, float e, float o) {
                *(uint32_t*)(vh2 + (size_t)r * KVE + n0 + cc) = pack_f16(e, o);
            });
    }
}

// ============================================================================
// output projection
// ============================================================================
__global__ __launch_bounds__(128, 2)
void wo_gemm(const __half* __restrict__ ao2, const __half* __restrict__ woh,
             float* __restrict__ out)
{
    const int n0 = blockIdx.x * 128;
    const int m0 = blockIdx.y * 128;
    gemm16_body(ao2, woh, m0, n0,
        [&](int r, int cc, float e, float o) {
            *(float2*)(out + (size_t)r * DMODEL + n0 + cc) = make_float2(e, o);
        });
}

// ============================================================================
// fp16 2-term tensor-core causal flash attention (Br=128, Bc=64)
// (unchanged — proven in R10/R11)
// ============================================================================
constexpr int ATT_STRIDE = 136;
constexpr int ROWB  = ATT_STRIDE * 2;        // 272 B
constexpr int QTILE = 128 * ROWB;            // 34816
constexpr int KTILE = 64 * ROWB;             // 17408
constexpr int KVSTAGE = 2 * KTILE;           // 34816
constexpr int ATT_SMEM = 4 * KVSTAGE;        // 139264

__global__ __launch_bounds__(256)
void attn_mma(const __half* __restrict__ Qh, const __half* __restrict__ Ql,
              const __half* __restrict__ Kh, const __half* __restrict__ Vh,
              __half* __restrict__ ao2)
{
    extern __shared__ char sm[];
    const uint32_t sb = smem_u32(sm);

    const int qb = gridDim.x - 1 - blockIdx.x;
    const int h  = blockIdx.y;
    const int b  = blockIdx.z;
    const int kh = h >> 2;
    const int tid = threadIdx.x;
    const int wid = tid >> 5;
    const int lane = tid & 31;
    const int q0 = qb * 128;
    const int nkb = q0 / 64 + 2;

    const int grp = lane >> 3, lr = lane & 7;

    {
        const size_t qrow = ((size_t)(b * SEQ + q0) * NH + h) * HD;
        for (int i = tid; i < 2048; i += 256) {
            int r = i >> 4, ch = i & 15;
            size_t g = qrow + (size_t)r * NH * HD + ch * 8;
            uint32_t so = r * ROWB + ch * 16;
            cp16(sb + so, Qh + g);
            cp16(sb + QTILE + so, Ql + g);
        }
    }
    asm volatile("cp.async.commit_group;" ::: "memory");
    asm volatile("cp.async.wait_group 0;" ::: "memory");
    __syncthreads();

    uint32_t qh_r[8][4], ql_r[8][4];
    {
        const uint32_t qa_h = sb + (wid * 16 + (grp & 1) * 8 + lr) * ROWB
                            + (grp >> 1) * 16;
        const uint32_t qa_l = qa_h + QTILE;
        #pragma unroll
        for (int ks = 0; ks < 8; ks++) {
            ldsm_x4(qh_r[ks], qa_h + ks * 32);
            ldsm_x4(ql_r[ks], qa_l + ks * 32);
        }
    }
    __syncthreads();

    auto issue_kv = [&](int kb) {
        const uint32_t st = sb + (kb & 3) * KVSTAGE;
        const size_t kvrow = ((size_t)(b * SEQ + kb * 64) * NKV + kh) * HD;
        for (int i = tid; i < 1024; i += 256) {
            int r = i >> 4, ch = i & 15;
            size_t g = kvrow + (size_t)r * NKV * HD + ch * 8;
            uint32_t so = r * ROWB + ch * 16;
            cp16(st + so,         Kh + g);
            cp16(st + KTILE + so, Vh + g);
        }
    };

    #pragma unroll
    for (int p = 0; p < 3; p++) {
        if (p < nkb) issue_kv(p);
        asm volatile("cp.async.commit_group;" ::: "memory");
    }

    const uint32_t kboff = ((grp >> 1) * 8 + lr) * ROWB + (grp & 1) * 16;
    const uint32_t vboff = ((grp & 1) * 8 + lr) * ROWB + (grp >> 1) * 16;

    float m_[2] = {-1e30f, -1e30f};
    float l_[2] = {0.f, 0.f};
    float of[16][4];
    #pragma unroll
    for (int nf = 0; nf < 16; nf++)
        #pragma unroll
        for (int e = 0; e < 4; e++) of[nf][e] = 0.f;

    const float scale = 0.08838834764831845f;
    const int rbase = q0 + wid * 16 + (lane >> 2);

    for (int kb = 0; kb < nkb; kb++) {
        asm volatile("cp.async.wait_group 2;" ::: "memory");
        __syncthreads();
        if (kb + 3 < nkb) issue_kv(kb + 3);
        asm volatile("cp.async.commit_group;" ::: "memory");

        const uint32_t st = sb + (kb & 3) * KVSTAGE;

        float sf[8][4];
        #pragma unroll
        for (int f = 0; f < 8; f++)
            #pragma unroll
            for (int e = 0; e < 4; e++) sf[f][e] = 0.f;

        {
            uint32_t bh0[4], bh1[4];
            ldsm_x4(bh0, st + kboff);
            #pragma unroll
            for (int t = 0; t < 32; t++) {
                const int ks = t >> 2, nb = t & 3;
                uint32_t* cur = (t & 1) ? bh1 : bh0;
                uint32_t* nxt = (t & 1) ? bh0 : bh1;
                if (t + 1 < 32) {
                    const int ks2 = (t + 1) >> 2, nb2 = (t + 1) & 3;
                    ldsm_x4(nxt, st + kboff + nb2 * 16 * ROWB + ks2 * 32);
                }
                mma_f16(sf[2 * nb],     qh_r[ks], cur);
                mma_f16(sf[2 * nb + 1], qh_r[ks], cur + 2);
                mma_f16(sf[2 * nb],     ql_r[ks], cur);
                mma_f16(sf[2 * nb + 1], ql_r[ks], cur + 2);
            }
        }

        float mx[2] = {-1e30f, -1e30f};
        #pragma unroll
        for (int f = 0; f < 8; f++)
            #pragma unroll
            for (int e = 0; e < 4; e++) {
                float v = sf[f][e] * scale;
                int col = kb * 64 + f * 8 + ((lane & 3) << 1) + (e & 1);
                int row = rbase + ((e & 2) << 2);
                v = (col > row) ? -1e30f : v;
                sf[f][e] = v;
                mx[e >> 1] = fmaxf(mx[e >> 1], v);
            }
        #pragma unroll
        for (int e = 0; e < 2; e++) {
            mx[e] = fmaxf(mx[e], __shfl_xor_sync(0xffffffffu, mx[e], 1));
            mx[e] = fmaxf(mx[e], __shfl_xor_sync(0xffffffffu, mx[e], 2));
        }
        float mn[2], alp[2], rs[2] = {0.f, 0.f};
        #pragma unroll
        for (int e = 0; e < 2; e++) {
            mn[e]  = fmaxf(m_[e], mx[e]);
            alp[e] = __expf(m_[e] - mn[e]);
            m_[e]  = mn[e];
        }
        #pragma unroll
        for (int f = 0; f < 8; f++)
            #pragma unroll
            for (int e = 0; e < 4; e++) {
                float p = __expf(sf[f][e] - mn[e >> 1]);
                sf[f][e] = p;
                rs[e >> 1] += p;
            }
        #pragma unroll
        for (int e = 0; e < 2; e++) {
            rs[e] += __shfl_xor_sync(0xffffffffu, rs[e], 1);
            rs[e] += __shfl_xor_sync(0xffffffffu, rs[e], 2);
            l_[e] = l_[e] * alp[e] + rs[e];
        }
        #pragma unroll
        for (int nf = 0; nf < 16; nf++) {
            of[nf][0] *= alp[0]; of[nf][1] *= alp[0];
            of[nf][2] *= alp[1]; of[nf][3] *= alp[1];
        }

        {
            uint32_t PH[4][4], PL[4][4];
            #pragma unroll
            for (int ks = 0; ks < 4; ks++) {
                split2h(sf[2 * ks][0],     sf[2 * ks][1],     PH[ks][0], PL[ks][0]);
                split2h(sf[2 * ks][2],     sf[2 * ks][3],     PH[ks][1], PL[ks][1]);
                split2h(sf[2 * ks + 1][0], sf[2 * ks + 1][1], PH[ks][2], PL[ks][2]);
                split2h(sf[2 * ks + 1][2], sf[2 * ks + 1][3], PH[ks][3], PL[ks][3]);
            }
            uint32_t vv0[4], vv1[4];
            ldsm_x4_t(vv0, st + KTILE + vboff);
            #pragma unroll
            for (int t = 0; t < 32; t++) {
                const int ks = t >> 3, nb = t & 7;
                uint32_t* cur = (t & 1) ? vv1 : vv0;
                uint32_t* nxt = (t & 1) ? vv0 : vv1;
                if (t + 1 < 32) {
                    const int ks2 = (t + 1) >> 3, nb2 = (t + 1) & 7;
                    ldsm_x4_t(nxt, st + KTILE + vboff + ks2 * 16 * ROWB + nb2 * 32);
                }
                mma_f16(of[2 * nb],     PH[ks], cur);
                mma_f16(of[2 * nb + 1], PH[ks], cur + 2);
                mma_f16(of[2 * nb],     PL[ks], cur);
                mma_f16(of[2 * nb + 1], PL[ks], cur + 2);
            }
        }
    }

    float inv0 = 1.f / l_[0], inv1 = 1.f / l_[1];
    size_t b0 = (size_t)(b * SEQ + rbase) * K2 + h * HD + ((lane & 3) << 1);
    size_t b1 = b0 + (size_t)8 * K2;
    #pragma unroll
    for (int nf = 0; nf < 16; nf++) {
        uint32_t hi, lo;
        split2h(of[nf][0] * inv0, of[nf][1] * inv0, hi, lo);
        *(uint32_t*)(ao2 + b0 + nf * 8)          = hi;
        *(uint32_t*)(ao2 + b0 + DMODEL + nf * 8) = lo;
        split2h(of[nf][2] * inv1, of[nf][3] * inv1, hi, lo);
        *(uint32_t*)(ao2 + b1 + nf * 8)          = hi;
        *(uint32_t*)(ao2 + b1 + DMODEL + nf * 8) = lo;
    }
}

// ============================================================================
// host launcher
// ============================================================================
extern "C" void kernel_launch(void* const* d_in, const int* in_sizes, int n_in,
                              void* d_out, int out_size)
{
    const float* x  = (const float*)d_in[0];
    const float* fc = (const float*)d_in[1];
    const float* fs = (const float*)d_in[2];
    const float* wq = (const float*)d_in[4];
    const float* wk = (const float*)d_in[5];
    const float* wv = (const float*)d_in[6];
    const float* wo = (const float*)d_in[7];
    float* out = (float*)d_out;

    __half *x2, *ao2, *wqh, *wkh, *wvh, *woh, *qh2, *ql2, *kh2, *vh2;
    cudaGetSymbolAddress((void**)&x2,  g_x2);
    cudaGetSymbolAddress((void**)&ao2, g_ao2);
    cudaGetSymbolAddress((void**)&wqh, g_wqh);
    cudaGetSymbolAddress((void**)&wkh, g_wkh);
    cudaGetSymbolAddress((void**)&wvh, g_wvh);
    cudaGetSymbolAddress((void**)&woh, g_woh);
    cudaGetSymbolAddress((void**)&qh2, g_qh2);
    cudaGetSymbolAddress((void**)&ql2, g_ql2);
    cudaGetSymbolAddress((void**)&kh2, g_kh2);
    cudaGetSymbolAddress((void**)&vh2, g_vh2);

    cudaFuncSetAttribute(qkv_gemm, cudaFuncAttributeMaxDynamicSharedMemorySize,
                         GEMM16_SMEM);
    cudaFuncSetAttribute(wo_gemm, cudaFuncAttributeMaxDynamicSharedMemorySize,
                         GEMM16_SMEM);
    cudaFuncSetAttribute(attn_mma, cudaFuncAttributeMaxDynamicSharedMemorySize,
                         ATT_SMEM);

    // ---- single merged conversion launch ----
    convert_all<<<(unsigned)(CQ_WO / 256), 256>>>(
        (const float4*)x, (const float4*)wq, (const float4*)wk,
        (const float4*)wv, (const float4*)wo, x2, wqh, wkh, wvh, woh);

    // ---- fused QKV projection + RoPE + fp16 split ----
    qkv_gemm<<<dim3(24, MROWS / 128), 128, GEMM16_SMEM>>>(
        x2, wqh, wkh, wvh, fc, fs, qh2, ql2, kh2, vh2);

    // ---- tensor-core causal attention ----
    attn_mma<<<dim3(SEQ / 128, NH, BB), 256, ATT_SMEM>>>(qh2, ql2, kh2, vh2, ao2);

    // ---- output projection ----
    wo_gemm<<<dim3(DMODEL / 128, MROWS / 128), 128, GEMM16_SMEM>>>(ao2, woh, out);
}

// round 15
// speedup vs baseline: 1.3290x; 1.2081x over previous
#include <cuda_runtime.h>
#include <cuda_fp16.h>
#include <math.h>
#include <cstdint>

// ---------------- problem constants ----------------
constexpr int BB     = 2;
constexpr int SEQ    = 2048;
constexpr int DMODEL = 2048;
constexpr int NH     = 16;
constexpr int NKV    = 4;
constexpr int HD     = 128;
constexpr int MROWS  = BB * SEQ;     // 4096
constexpr int QE     = NH * HD;      // 2048
constexpr int KVE    = NKV * HD;     // 512
constexpr int K2     = 4096;         // x stored [hi(2048) | lo(2048)]

// ---------------- scratch ----------------
__device__ __half g_x2 [(size_t)MROWS * K2];    // [xh | xl]
__device__ __half g_aoh[(size_t)MROWS * QE];    // attention out, hi only
__device__ __half g_wqh[(size_t)QE     * DMODEL];
__device__ __half g_wkh[(size_t)KVE    * DMODEL];
__device__ __half g_wvh[(size_t)KVE    * DMODEL];
__device__ __half g_woh[(size_t)DMODEL * DMODEL];

__device__ __half g_qh2[(size_t)MROWS * QE];
__device__ __half g_ql2[(size_t)MROWS * QE];
__device__ __half g_kh2[(size_t)MROWS * KVE];
__device__ __half g_vh2[(size_t)MROWS * KVE];

// ---------------- helpers ----------------
__device__ __forceinline__ uint32_t smem_u32(const void* p) {
    uint32_t a;
    asm("{ .reg .u64 t; cvta.to.shared.u64 t, %1; cvt.u32.u64 %0, t; }"
        : "=r"(a) : "l"(p));
    return a;
}
__device__ __forceinline__ void cp16(uint32_t dst, const void* src) {
    asm volatile("cp.async.cg.shared.global [%0], [%1], 16;"
                 :: "r"(dst), "l"(src));
}
__device__ __forceinline__ void ldsm_x4(uint32_t* r, uint32_t addr) {
    asm volatile("ldmatrix.sync.aligned.m8n8.x4.shared.b16 {%0,%1,%2,%3}, [%4];"
                 : "=r"(r[0]), "=r"(r[1]), "=r"(r[2]), "=r"(r[3]) : "r"(addr));
}
__device__ __forceinline__ void ldsm_x4_t(uint32_t* r, uint32_t addr) {
    asm volatile("ldmatrix.sync.aligned.m8n8.x4.trans.shared.b16 {%0,%1,%2,%3}, [%4];"
                 : "=r"(r[0]), "=r"(r[1]), "=r"(r[2]), "=r"(r[3]) : "r"(addr));
}
__device__ __forceinline__ void mma_f16(float* d, const uint32_t* a,
                                        const uint32_t* b) {
    asm volatile(
        "mma.sync.aligned.m16n8k16.row.col.f32.f16.f16.f32 "
        "{%0,%1,%2,%3}, {%4,%5,%6,%7}, {%8,%9}, {%0,%1,%2,%3};"
        : "+f"(d[0]), "+f"(d[1]), "+f"(d[2]), "+f"(d[3])
        : "r"(a[0]), "r"(a[1]), "r"(a[2]), "r"(a[3]), "r"(b[0]), "r"(b[1]));
}
__device__ __forceinline__ uint32_t pack_f16(float lo, float hi) {
    uint32_t r;
    asm("cvt.rn.f16x2.f32 %0, %1, %2;" : "=r"(r) : "f"(hi), "f"(lo));
    return r;
}
__device__ __forceinline__ void split2h(float x, float y, uint32_t& hi, uint32_t& lo) {
    uint32_t h = pack_f16(x, y);
    __half2 hb = *reinterpret_cast<__half2*>(&h);
    lo = pack_f16(x - __half2float(hb.x), y - __half2float(hb.y));
    hi = h;
}

// ============================================================================
// merged conversion kernel
// ============================================================================
constexpr size_t CQ_X  = 2097152;
constexpr size_t CQ_WQ = CQ_X  + 1048576;
constexpr size_t CQ_WK = CQ_WQ + 262144;
constexpr size_t CQ_WV = CQ_WK + 262144;
constexpr size_t CQ_WO = CQ_WV + 1048576;

__global__ __launch_bounds__(256)
void convert_all(const float4* __restrict__ x,  const float4* __restrict__ wq,
                 const float4* __restrict__ wk, const float4* __restrict__ wv,
                 const float4* __restrict__ wo,
                 __half* __restrict__ x2,  __half* __restrict__ wqh,
                 __half* __restrict__ wkh, __half* __restrict__ wvh,
                 __half* __restrict__ woh)
{
    size_t i = (size_t)blockIdx.x * 256 + threadIdx.x;
    if (i < CQ_X) {
        float4 v = x[i];
        size_t e = i * 4;
        size_t r = e >> 11;
        int    c = (int)(e & 2047);
        float xs[4] = {v.x, v.y, v.z, v.w};
        __half* d = x2 + r * (size_t)K2 + c;
        #pragma unroll
        for (int j = 0; j < 4; j++) {
            __half h = __float2half(xs[j]);
            d[j]          = h;
            d[DMODEL + j] = __float2half(xs[j] - __half2float(h));
        }
        return;
    }
    const float4* src; __half* dst; size_t j;
    if      (i < CQ_WQ) { src = wq; dst = wqh; j = i - CQ_X;  }
    else if (i < CQ_WK) { src = wk; dst = wkh; j = i - CQ_WQ; }
    else if (i < CQ_WV) { src = wv; dst = wvh; j = i - CQ_WK; }
    else                { src = wo; dst = woh; j = i - CQ_WV; }
    float4 v = src[j];
    size_t e = j * 4;
    dst[e]     = __float2half(v.x);
    dst[e + 1] = __float2half(v.y);
    dst[e + 2] = __float2half(v.z);
    dst[e + 3] = __float2half(v.w);
}

// ============================================================================
// GEMM — R14 configuration; chunk count templated (128 = 2-term A, 64 = 1-term)
// ============================================================================
constexpr int HROWB  = 80;                 // bytes per smem row (40 halves)
constexpr int GTILE  = 128 * HROWB;        // 10240 B
constexpr int GSTAGE = 2 * GTILE;          // A + B
constexpr int GEMM16_SMEM = 4 * GSTAGE;    // 81920

template <int NCH_T, typename EPI>
__device__ __forceinline__
void gemm16_body(const __half* __restrict__ A, int a_stride,
                 const __half* __restrict__ Bw,
                 int m0, int n0loc, EPI epi)
{
    extern __shared__ char sm[];
    const uint32_t sb = smem_u32(sm);
    const int tid = threadIdx.x;
    const int wid = tid >> 5;
    const int lane = tid & 31;
    const int wm = (wid >> 1) * 64;
    const int wn = (wid & 1) * 64;

    const __half* Abase = A  + (size_t)m0 * a_stride;
    const __half* Bbase = Bw + (size_t)n0loc * DMODEL;

    const int grp = lane >> 3, lr = lane & 7;
    const uint32_t aoff0 = (wm + (grp & 1) * 8 + lr) * HROWB + (grp >> 1) * 16;
    const uint32_t boff0 = GTILE + (wn + (grp >> 1) * 8 + lr) * HROWB
                         + (grp & 1) * 16;

    float acc[4][8][4];
    #pragma unroll
    for (int mf = 0; mf < 4; mf++)
        #pragma unroll
        for (int nf = 0; nf < 8; nf++)
            #pragma unroll
            for (int e = 0; e < 4; e++) acc[mf][nf][e] = 0.f;

    auto issue = [&](int c) {
        if (c >= NCH_T) return;
        const uint32_t st = sb + (c & 3) * GSTAGE;
        const __half* Ag = Abase + c * 32;
        const __half* Bg = Bbase + (c & 63) * 32;
        #pragma unroll
        for (int t = 0; t < 4; t++) {
            int i = tid + t * 128;
            int row = i >> 2, seg = i & 3;
            cp16(st + row * HROWB + seg * 16,
                 Ag + (size_t)row * a_stride + seg * 8);
        }
        #pragma unroll
        for (int t = 0; t < 4; t++) {
            int i = tid + t * 128;
            int row = i >> 2, seg = i & 3;
            cp16(st + GTILE + row * HROWB + seg * 16,
                 Bg + (size_t)row * DMODEL + seg * 8);
        }
    };

    issue(0); asm volatile("cp.async.commit_group;" ::: "memory");
    issue(1); asm volatile("cp.async.commit_group;" ::: "memory");
    issue(2); asm volatile("cp.async.commit_group;" ::: "memory");

    uint32_t arA[4][4], brA[4][4], arB[4][4], brB[4][4];

    for (int c = 0; c < NCH_T; c++) {
        asm volatile("cp.async.wait_group 2;" ::: "memory");
        __syncthreads();
        issue(c + 3);
        asm volatile("cp.async.commit_group;" ::: "memory");

        const uint32_t st = sb + (c & 3) * GSTAGE;

        #pragma unroll
        for (int mf = 0; mf < 4; mf++)
            ldsm_x4(arA[mf], st + aoff0 + mf * (16 * HROWB));
        #pragma unroll
        for (int nf2 = 0; nf2 < 4; nf2++)
            ldsm_x4(brA[nf2], st + boff0 + nf2 * (16 * HROWB));

        #pragma unroll
        for (int mf = 0; mf < 4; mf++) {
            ldsm_x4(arB[mf], st + aoff0 + mf * (16 * HROWB) + 32);
            #pragma unroll
            for (int nf = 0; nf < 4; nf++)
                mma_f16(acc[mf][nf], arA[mf], &brA[nf >> 1][(nf & 1) * 2]);
            ldsm_x4(brB[mf], st + boff0 + mf * (16 * HROWB) + 32);
            #pragma unroll
            for (int nf = 4; nf < 8; nf++)
                mma_f16(acc[mf][nf], arA[mf], &brA[nf >> 1][(nf & 1) * 2]);
        }

        #pragma unroll
        for (int mf = 0; mf < 4; mf++)
            #pragma unroll
            for (int nf = 0; nf < 8; nf++)
                mma_f16(acc[mf][nf], arB[mf], &brB[nf >> 1][(nf & 1) * 2]);
    }

    const int lr4 = lane >> 2, lc2 = (lane & 3) * 2;
    #pragma unroll
    for (int mf = 0; mf < 4; mf++) {
        int r = m0 + wm + mf * 16 + lr4;
        #pragma unroll
        for (int nf = 0; nf < 8; nf++) {
            int cc = wn + nf * 8 + lc2;
            epi(r,     cc, acc[mf][nf][0], acc[mf][nf][1]);
            epi(r + 8, cc, acc[mf][nf][2], acc[mf][nf][3]);
        }
    }
}

// ============================================================================
// fused QKV projection: Q = 2-term (128 chunks), K/V = 1-term (64 chunks)
// ============================================================================
__global__ __launch_bounds__(128, 2)
void qkv_gemm(const __half* __restrict__ x2,
              const __half* __restrict__ wqh, const __half* __restrict__ wkh,
              const __half* __restrict__ wvh,
              const float* __restrict__ fc, const float* __restrict__ fs,
              __half* __restrict__ qh2, __half* __restrict__ ql2,
              __half* __restrict__ kh2, __half* __restrict__ vh2)
{
    const int bx = blockIdx.x;
    const int m0 = blockIdx.y * 128;

    if (bx < 16) {             // Q: 2-term A
        const int n0 = bx * 128;
        gemm16_body<128>(x2, K2, wqh, m0, n0,
            [&](int r, int cc, float e, float o) {
                int col = n0 + cc;
                int s = r & (SEQ - 1);
                int p = (col & 127) >> 1;
                float c  = fc[s * 64 + p];
                float si = fs[s * 64 + p];
                float re = e * c - o * si;
                float ro = e * si + o * c;
                uint32_t hi, lo;
                split2h(re, ro, hi, lo);
                size_t idx = (size_t)r * QE + col;
                *(uint32_t*)(qh2 + idx) = hi;
                *(uint32_t*)(ql2 + idx) = lo;
            });
    } else if (bx < 20) {      // K: 1-term A (hi only)
        const int n0 = (bx - 16) * 128;
        gemm16_body<64>(x2, K2, wkh, m0, n0,
            [&](int r, int cc, float e, float o) {
                int col = n0 + cc;
                int s = r & (SEQ - 1);
                int p = (col & 127) >> 1;
                float c  = fc[s * 64 + p];
                float si = fs[s * 64 + p];
                float re = e * c - o * si;
                float ro = e * si + o * c;
                *(uint32_t*)(kh2 + (size_t)r * KVE + col) = pack_f16(re, ro);
            });
    } else {                   // V: 1-term A
        const int n0 = (bx - 20) * 128;
        gemm16_body<64>(x2, K2, wvh, m0, n0,
            [&](int r, int cc, float e, float o) {
                *(uint32_t*)(vh2 + (size_t)r * KVE + n0 + cc) = pack_f16(e, o);
            });
    }
}

// ============================================================================
// output projection: 1-term A (aoh only, stride QE)
// ============================================================================
__global__ __launch_bounds__(128, 2)
void wo_gemm(const __half* __restrict__ aoh, const __half* __restrict__ woh,
             float* __restrict__ out)
{
    const int n0 = blockIdx.x * 128;
    const int m0 = blockIdx.y * 128;
    gemm16_body<64>(aoh, QE, woh, m0, n0,
        [&](int r, int cc, float e, float o) {
            *(float2*)(out + (size_t)r * DMODEL + n0 + cc) = make_float2(e, o);
        });
}

// ============================================================================
// fp16 2-term tensor-core causal flash attention (Br=128, Bc=64)
// epilogue writes hi only (wo projection is 1-term now)
// ============================================================================
constexpr int ATT_STRIDE = 136;
constexpr int ROWB  = ATT_STRIDE * 2;        // 272 B
constexpr int QTILE = 128 * ROWB;            // 34816
constexpr int KTILE = 64 * ROWB;             // 17408
constexpr int KVSTAGE = 2 * KTILE;           // 34816
constexpr int ATT_SMEM = 4 * KVSTAGE;        // 139264

__global__ __launch_bounds__(256)
void attn_mma(const __half* __restrict__ Qh, const __half* __restrict__ Ql,
              const __half* __restrict__ Kh, const __half* __restrict__ Vh,
              __half* __restrict__ aoh)
{
    extern __shared__ char sm[];
    const uint32_t sb = smem_u32(sm);

    const int qb = gridDim.x - 1 - blockIdx.x;
    const int h  = blockIdx.y;
    const int b  = blockIdx.z;
    const int kh = h >> 2;
    const int tid = threadIdx.x;
    const int wid = tid >> 5;
    const int lane = tid & 31;
    const int q0 = qb * 128;
    const int nkb = q0 / 64 + 2;

    const int grp = lane >> 3, lr = lane & 7;

    {
        const size_t qrow = ((size_t)(b * SEQ + q0) * NH + h) * HD;
        for (int i = tid; i < 2048; i += 256) {
            int r = i >> 4, ch = i & 15;
            size_t g = qrow + (size_t)r * NH * HD + ch * 8;
            uint32_t so = r * ROWB + ch * 16;
            cp16(sb + so, Qh + g);
            cp16(sb + QTILE + so, Ql + g);
        }
    }
    asm volatile("cp.async.commit_group;" ::: "memory");
    asm volatile("cp.async.wait_group 0;" ::: "memory");
    __syncthreads();

    uint32_t qh_r[8][4], ql_r[8][4];
    {
        const uint32_t qa_h = sb + (wid * 16 + (grp & 1) * 8 + lr) * ROWB
                            + (grp >> 1) * 16;
        const uint32_t qa_l = qa_h + QTILE;
        #pragma unroll
        for (int ks = 0; ks < 8; ks++) {
            ldsm_x4(qh_r[ks], qa_h + ks * 32);
            ldsm_x4(ql_r[ks], qa_l + ks * 32);
        }
    }
    __syncthreads();

    auto issue_kv = [&](int kb) {
        const uint32_t st = sb + (kb & 3) * KVSTAGE;
        const size_t kvrow = ((size_t)(b * SEQ + kb * 64) * NKV + kh) * HD;
        for (int i = tid; i < 1024; i += 256) {
            int r = i >> 4, ch = i & 15;
            size_t g = kvrow + (size_t)r * NKV * HD + ch * 8;
            uint32_t so = r * ROWB + ch * 16;
            cp16(st + so,         Kh + g);
            cp16(st + KTILE + so, Vh + g);
        }
    };

    #pragma unroll
    for (int p = 0; p < 3; p++) {
        if (p < nkb) issue_kv(p);
        asm volatile("cp.async.commit_group;" ::: "memory");
    }

    const uint32_t kboff = ((grp >> 1) * 8 + lr) * ROWB + (grp & 1) * 16;
    const uint32_t vboff = ((grp & 1) * 8 + lr) * ROWB + (grp >> 1) * 16;

    float m_[2] = {-1e30f, -1e30f};
    float l_[2] = {0.f, 0.f};
    float of[16][4];
    #pragma unroll
    for (int nf = 0; nf < 16; nf++)
        #pragma unroll
        for (int e = 0; e < 4; e++) of[nf][e] = 0.f;

    const float scale = 0.08838834764831845f;
    const int rbase = q0 + wid * 16 + (lane >> 2);

    for (int kb = 0; kb < nkb; kb++) {
        asm volatile("cp.async.wait_group 2;" ::: "memory");
        __syncthreads();
        if (kb + 3 < nkb) issue_kv(kb + 3);
        asm volatile("cp.async.commit_group;" ::: "memory");

        const uint32_t st = sb + (kb & 3) * KVSTAGE;

        float sf[8][4];
        #pragma unroll
        for (int f = 0; f < 8; f++)
            #pragma unroll
            for (int e = 0; e < 4; e++) sf[f][e] = 0.f;

        {
            uint32_t bh0[4], bh1[4];
            ldsm_x4(bh0, st + kboff);
            #pragma unroll
            for (int t = 0; t < 32; t++) {
                const int ks = t >> 2, nb = t & 3;
                uint32_t* cur = (t & 1) ? bh1 : bh0;
                uint32_t* nxt = (t & 1) ? bh0 : bh1;
                if (t + 1 < 32) {
                    const int ks2 = (t + 1) >> 2, nb2 = (t + 1) & 3;
                    ldsm_x4(nxt, st + kboff + nb2 * 16 * ROWB + ks2 * 32);
                }
                mma_f16(sf[2 * nb],     qh_r[ks], cur);
                mma_f16(sf[2 * nb + 1], qh_r[ks], cur + 2);
                mma_f16(sf[2 * nb],     ql_r[ks], cur);
                mma_f16(sf[2 * nb + 1], ql_r[ks], cur + 2);
            }
        }

        float mx[2] = {-1e30f, -1e30f};
        #pragma unroll
        for (int f = 0; f < 8; f++)
            #pragma unroll
            for (int e = 0; e < 4; e++) {
                float v = sf[f][e] * scale;
                int col = kb * 64 + f * 8 + ((lane & 3) << 1) + (e & 1);
                int row = rbase + ((e & 2) << 2);
                v = (col > row) ? -1e30f : v;
                sf[f][e] = v;
                mx[e >> 1] = fmaxf(mx[e >> 1], v);
            }
        #pragma unroll
        for (int e = 0; e < 2; e++) {
            mx[e] = fmaxf(mx[e], __shfl_xor_sync(0xffffffffu, mx[e], 1));
            mx[e] = fmaxf(mx[e], __shfl_xor_sync(0xffffffffu, mx[e], 2));
        }
        float mn[2], alp[2], rs[2] = {0.f, 0.f};
        #pragma unroll
        for (int e = 0; e < 2; e++) {
            mn[e]  = fmaxf(m_[e], mx[e]);
            alp[e] = __expf(m_[e] - mn[e]);
            m_[e]  = mn[e];
        }
        #pragma unroll
        for (int f = 0; f < 8; f++)
            #pragma unroll
            for (int e = 0; e < 4; e++) {
                float p = __expf(sf[f][e] - mn[e >> 1]);
                sf[f][e] = p;
                rs[e >> 1] += p;
            }
        #pragma unroll
        for (int e = 0; e < 2; e++) {
            rs[e] += __shfl_xor_sync(0xffffffffu, rs[e], 1);
            rs[e] += __shfl_xor_sync(0xffffffffu, rs[e], 2);
            l_[e] = l_[e] * alp[e] + rs[e];
        }
        #pragma unroll
        for (int nf = 0; nf < 16; nf++) {
            of[nf][0] *= alp[0]; of[nf][1] *= alp[0];
            of[nf][2] *= alp[1]; of[nf][3] *= alp[1];
        }

        {
            uint32_t PH[4][4], PL[4][4];
            #pragma unroll
            for (int ks = 0; ks < 4; ks++) {
                split2h(sf[2 * ks][0],     sf[2 * ks][1],     PH[ks][0], PL[ks][0]);
                split2h(sf[2 * ks][2],     sf[2 * ks][3],     PH[ks][1], PL[ks][1]);
                split2h(sf[2 * ks + 1][0], sf[2 * ks + 1][1], PH[ks][2], PL[ks][2]);
                split2h(sf[2 * ks + 1][2], sf[2 * ks + 1][3], PH[ks][3], PL[ks][3]);
            }
            uint32_t vv0[4], vv1[4];
            ldsm_x4_t(vv0, st + KTILE + vboff);
            #pragma unroll
            for (int t = 0; t < 32; t++) {
                const int ks = t >> 3, nb = t & 7;
                uint32_t* cur = (t & 1) ? vv1 : vv0;
                uint32_t* nxt = (t & 1) ? vv0 : vv1;
                if (t + 1 < 32) {
                    const int ks2 = (t + 1) >> 3, nb2 = (t + 1) & 7;
                    ldsm_x4_t(nxt, st + KTILE + vboff + ks2 * 16 * ROWB + nb2 * 32);
                }
                mma_f16(of[2 * nb],     PH[ks], cur);
                mma_f16(of[2 * nb + 1], PH[ks], cur + 2);
                mma_f16(of[2 * nb],     PL[ks], cur);
                mma_f16(of[2 * nb + 1], PL[ks], cur + 2);
            }
        }
    }

    // ---- epilogue: normalize, write hi only ----
    float inv0 = 1.f / l_[0], inv1 = 1.f / l_[1];
    size_t b0 = (size_t)(b * SEQ + rbase) * QE + h * HD + ((lane & 3) << 1);
    size_t b1 = b0 + (size_t)8 * QE;
    #pragma unroll
    for (int nf = 0; nf < 16; nf++) {
        *(uint32_t*)(aoh + b0 + nf * 8) = pack_f16(of[nf][0] * inv0, of[nf][1] * inv0);
        *(uint32_t*)(aoh + b1 + nf * 8) = pack_f16(of[nf][2] * inv1, of[nf][3] * inv1);
    }
}

// ============================================================================
// host launcher
// ============================================================================
extern "C" void kernel_launch(void* const* d_in, const int* in_sizes, int n_in,
                              void* d_out, int out_size)
{
    const float* x  = (const float*)d_in[0];
    const float* fc = (const float*)d_in[1];
    const float* fs = (const float*)d_in[2];
    const float* wq = (const float*)d_in[4];
    const float* wk = (const float*)d_in[5];
    const float* wv = (const float*)d_in[6];
    const float* wo = (const float*)d_in[7];
    float* out = (float*)d_out;

    __half *x2, *aoh, *wqh, *wkh, *wvh, *woh, *qh2, *ql2, *kh2, *vh2;
    cudaGetSymbolAddress((void**)&x2,  g_x2);
    cudaGetSymbolAddress((void**)&aoh, g_aoh);
    cudaGetSymbolAddress((void**)&wqh, g_wqh);
    cudaGetSymbolAddress((void**)&wkh, g_wkh);
    cudaGetSymbolAddress((void**)&wvh, g_wvh);
    cudaGetSymbolAddress((void**)&woh, g_woh);
    cudaGetSymbolAddress((void**)&qh2, g_qh2);
    cudaGetSymbolAddress((void**)&ql2, g_ql2);
    cudaGetSymbolAddress((void**)&kh2, g_kh2);
    cudaGetSymbolAddress((void**)&vh2, g_vh2);

    cudaFuncSetAttribute(qkv_gemm, cudaFuncAttributeMaxDynamicSharedMemorySize,
                         GEMM16_SMEM);
    cudaFuncSetAttribute(wo_gemm, cudaFuncAttributeMaxDynamicSharedMemorySize,
                         GEMM16_SMEM);
    cudaFuncSetAttribute(attn_mma, cudaFuncAttributeMaxDynamicSharedMemorySize,
                         ATT_SMEM);

    // ---- single merged conversion launch ----
    convert_all<<<(unsigned)(CQ_WO / 256), 256>>>(
        (const float4*)x, (const float4*)wq, (const float4*)wk,
        (const float4*)wv, (const float4*)wo, x2, wqh, wkh, wvh, woh);

    // ---- fused QKV projection + RoPE + fp16 split ----
    qkv_gemm<<<dim3(24, MROWS / 128), 128, GEMM16_SMEM>>>(
        x2, wqh, wkh, wvh, fc, fs, qh2, ql2, kh2, vh2);

    // ---- tensor-core causal attention ----
    attn_mma<<<dim3(SEQ / 128, NH, BB), 256, ATT_SMEM>>>(qh2, ql2, kh2, vh2, aoh);

    // ---- output projection (1-term) ----
    wo_gemm<<<dim3(DMODEL / 128, MROWS / 128), 128, GEMM16_SMEM>>>(aoh, woh, out);
}

// round 16
// speedup vs baseline: 1.3941x; 1.0489x over previous
#include <cuda_runtime.h>
#include <cuda_fp16.h>
#include <math.h>
#include <cstdint>

// ---------------- problem constants ----------------
constexpr int BB     = 2;
constexpr int SEQ    = 2048;
constexpr int DMODEL = 2048;
constexpr int NH     = 16;
constexpr int NKV    = 4;
constexpr int HD     = 128;
constexpr int MROWS  = BB * SEQ;     // 4096
constexpr int QE     = NH * HD;      // 2048
constexpr int KVE    = NKV * HD;     // 512
constexpr int K2     = 4096;         // x stored [hi(2048) | lo(2048)]

// ---------------- scratch ----------------
__device__ __half g_x2 [(size_t)MROWS * K2];
__device__ __half g_aoh[(size_t)MROWS * QE];
__device__ __half g_wqh[(size_t)QE     * DMODEL];
__device__ __half g_wkh[(size_t)KVE    * DMODEL];
__device__ __half g_wvh[(size_t)KVE    * DMODEL];
__device__ __half g_woh[(size_t)DMODEL * DMODEL];

__device__ __half g_qh2[(size_t)MROWS * QE];
__device__ __half g_ql2[(size_t)MROWS * QE];
__device__ __half g_kh2[(size_t)MROWS * KVE];
__device__ __half g_vh2[(size_t)MROWS * KVE];

// ---------------- helpers ----------------
__device__ __forceinline__ uint32_t smem_u32(const void* p) {
    uint32_t a;
    asm("{ .reg .u64 t; cvta.to.shared.u64 t, %1; cvt.u32.u64 %0, t; }"
        : "=r"(a) : "l"(p));
    return a;
}
__device__ __forceinline__ void cp16(uint32_t dst, const void* src) {
    asm volatile("cp.async.cg.shared.global [%0], [%1], 16;"
                 :: "r"(dst), "l"(src));
}
__device__ __forceinline__ void ldsm_x4(uint32_t* r, uint32_t addr) {
    asm volatile("ldmatrix.sync.aligned.m8n8.x4.shared.b16 {%0,%1,%2,%3}, [%4];"
                 : "=r"(r[0]), "=r"(r[1]), "=r"(r[2]), "=r"(r[3]) : "r"(addr));
}
__device__ __forceinline__ void ldsm_x4_t(uint32_t* r, uint32_t addr) {
    asm volatile("ldmatrix.sync.aligned.m8n8.x4.trans.shared.b16 {%0,%1,%2,%3}, [%4];"
                 : "=r"(r[0]), "=r"(r[1]), "=r"(r[2]), "=r"(r[3]) : "r"(addr));
}
__device__ __forceinline__ void mma_f16(float* d, const uint32_t* a,
                                        const uint32_t* b) {
    asm volatile(
        "mma.sync.aligned.m16n8k16.row.col.f32.f16.f16.f32 "
        "{%0,%1,%2,%3}, {%4,%5,%6,%7}, {%8,%9}, {%0,%1,%2,%3};"
        : "+f"(d[0]), "+f"(d[1]), "+f"(d[2]), "+f"(d[3])
        : "r"(a[0]), "r"(a[1]), "r"(a[2]), "r"(a[3]), "r"(b[0]), "r"(b[1]));
}
__device__ __forceinline__ uint32_t pack_f16(float lo, float hi) {
    uint32_t r;
    asm("cvt.rn.f16x2.f32 %0, %1, %2;" : "=r"(r) : "f"(hi), "f"(lo));
    return r;
}
__device__ __forceinline__ void split2h(float x, float y, uint32_t& hi, uint32_t& lo) {
    uint32_t h = pack_f16(x, y);
    __half2 hb = *reinterpret_cast<__half2*>(&h);
    lo = pack_f16(x - __half2float(hb.x), y - __half2float(hb.y));
    hi = h;
}

// ============================================================================
// merged conversion kernel
// ============================================================================
constexpr size_t CQ_X  = 2097152;
constexpr size_t CQ_WQ = CQ_X  + 1048576;
constexpr size_t CQ_WK = CQ_WQ + 262144;
constexpr size_t CQ_WV = CQ_WK + 262144;
constexpr size_t CQ_WO = CQ_WV + 1048576;

__global__ __launch_bounds__(256)
void convert_all(const float4* __restrict__ x,  const float4* __restrict__ wq,
                 const float4* __restrict__ wk, const float4* __restrict__ wv,
                 const float4* __restrict__ wo,
                 __half* __restrict__ x2,  __half* __restrict__ wqh,
                 __half* __restrict__ wkh, __half* __restrict__ wvh,
                 __half* __restrict__ woh)
{
    size_t i = (size_t)blockIdx.x * 256 + threadIdx.x;
    if (i < CQ_X) {
        float4 v = x[i];
        size_t e = i * 4;
        size_t r = e >> 11;
        int    c = (int)(e & 2047);
        float xs[4] = {v.x, v.y, v.z, v.w};
        __half* d = x2 + r * (size_t)K2 + c;
        #pragma unroll
        for (int j = 0; j < 4; j++) {
            __half h = __float2half(xs[j]);
            d[j]          = h;
            d[DMODEL + j] = __float2half(xs[j] - __half2float(h));
        }
        return;
    }
    const float4* src; __half* dst; size_t j;
    if      (i < CQ_WQ) { src = wq; dst = wqh; j = i - CQ_X;  }
    else if (i < CQ_WK) { src = wk; dst = wkh; j = i - CQ_WQ; }
    else if (i < CQ_WV) { src = wv; dst = wvh; j = i - CQ_WK; }
    else                { src = wo; dst = woh; j = i - CQ_WV; }
    float4 v = src[j];
    size_t e = j * 4;
    dst[e]     = __float2half(v.x);
    dst[e + 1] = __float2half(v.y);
    dst[e + 2] = __float2half(v.z);
    dst[e + 3] = __float2half(v.w);
}

// ============================================================================
// GEMM (unchanged from R15 passing): 4 warps, 64x64 warp tiles, templated K
// ============================================================================
constexpr int HROWB  = 80;
constexpr int GTILE  = 128 * HROWB;        // 10240 B
constexpr int GSTAGE = 2 * GTILE;
constexpr int GEMM16_SMEM = 4 * GSTAGE;    // 81920

template <int NCH_T, typename EPI>
__device__ __forceinline__
void gemm16_body(const __half* __restrict__ A, int a_stride,
                 const __half* __restrict__ Bw,
                 int m0, int n0loc, EPI epi)
{
    extern __shared__ char sm[];
    const uint32_t sb = smem_u32(sm);
    const int tid = threadIdx.x;
    const int wid = tid >> 5;
    const int lane = tid & 31;
    const int wm = (wid >> 1) * 64;
    const int wn = (wid & 1) * 64;

    const __half* Abase = A  + (size_t)m0 * a_stride;
    const __half* Bbase = Bw + (size_t)n0loc * DMODEL;

    const int grp = lane >> 3, lr = lane & 7;
    const uint32_t aoff0 = (wm + (grp & 1) * 8 + lr) * HROWB + (grp >> 1) * 16;
    const uint32_t boff0 = GTILE + (wn + (grp >> 1) * 8 + lr) * HROWB
                         + (grp & 1) * 16;

    float acc[4][8][4];
    #pragma unroll
    for (int mf = 0; mf < 4; mf++)
        #pragma unroll
        for (int nf = 0; nf < 8; nf++)
            #pragma unroll
            for (int e = 0; e < 4; e++) acc[mf][nf][e] = 0.f;

    auto issue = [&](int c) {
        if (c >= NCH_T) return;
        const uint32_t st = sb + (c & 3) * GSTAGE;
        const __half* Ag = Abase + c * 32;
        const __half* Bg = Bbase + (c & 63) * 32;
        #pragma unroll
        for (int t = 0; t < 4; t++) {
            int i = tid + t * 128;
            int row = i >> 2, seg = i & 3;
            cp16(st + row * HROWB + seg * 16,
                 Ag + (size_t)row * a_stride + seg * 8);
        }
        #pragma unroll
        for (int t = 0; t < 4; t++) {
            int i = tid + t * 128;
            int row = i >> 2, seg = i & 3;
            cp16(st + GTILE + row * HROWB + seg * 16,
                 Bg + (size_t)row * DMODEL + seg * 8);
        }
    };

    issue(0); asm volatile("cp.async.commit_group;" ::: "memory");
    issue(1); asm volatile("cp.async.commit_group;" ::: "memory");
    issue(2); asm volatile("cp.async.commit_group;" ::: "memory");

    uint32_t arA[4][4], brA[4][4], arB[4][4], brB[4][4];

    for (int c = 0; c < NCH_T; c++) {
        asm volatile("cp.async.wait_group 2;" ::: "memory");
        __syncthreads();
        issue(c + 3);
        asm volatile("cp.async.commit_group;" ::: "memory");

        const uint32_t st = sb + (c & 3) * GSTAGE;

        #pragma unroll
        for (int mf = 0; mf < 4; mf++)
            ldsm_x4(arA[mf], st + aoff0 + mf * (16 * HROWB));
        #pragma unroll
        for (int nf2 = 0; nf2 < 4; nf2++)
            ldsm_x4(brA[nf2], st + boff0 + nf2 * (16 * HROWB));

        #pragma unroll
        for (int mf = 0; mf < 4; mf++) {
            ldsm_x4(arB[mf], st + aoff0 + mf * (16 * HROWB) + 32);
            #pragma unroll
            for (int nf = 0; nf < 4; nf++)
                mma_f16(acc[mf][nf], arA[mf], &brA[nf >> 1][(nf & 1) * 2]);
            ldsm_x4(brB[mf], st + boff0 + mf * (16 * HROWB) + 32);
            #pragma unroll
            for (int nf = 4; nf < 8; nf++)
                mma_f16(acc[mf][nf], arA[mf], &brA[nf >> 1][(nf & 1) * 2]);
        }

        #pragma unroll
        for (int mf = 0; mf < 4; mf++)
            #pragma unroll
            for (int nf = 0; nf < 8; nf++)
                mma_f16(acc[mf][nf], arB[mf], &brB[nf >> 1][(nf & 1) * 2]);
    }

    const int lr4 = lane >> 2, lc2 = (lane & 3) * 2;
    #pragma unroll
    for (int mf = 0; mf < 4; mf++) {
        int r = m0 + wm + mf * 16 + lr4;
        #pragma unroll
        for (int nf = 0; nf < 8; nf++) {
            int cc = wn + nf * 8 + lc2;
            epi(r,     cc, acc[mf][nf][0], acc[mf][nf][1]);
            epi(r + 8, cc, acc[mf][nf][2], acc[mf][nf][3]);
        }
    }
}

// ============================================================================
// fused QKV projection: Q = 2-term, K/V = 1-term
// ============================================================================
__global__ __launch_bounds__(128, 2)
void qkv_gemm(const __half* __restrict__ x2,
              const __half* __restrict__ wqh, const __half* __restrict__ wkh,
              const __half* __restrict__ wvh,
              const float* __restrict__ fc, const float* __restrict__ fs,
              __half* __restrict__ qh2, __half* __restrict__ ql2,
              __half* __restrict__ kh2, __half* __restrict__ vh2)
{
    const int bx = blockIdx.x;
    const int m0 = blockIdx.y * 128;

    if (bx < 16) {
        const int n0 = bx * 128;
        gemm16_body<128>(x2, K2, wqh, m0, n0,
            [&](int r, int cc, float e, float o) {
                int col = n0 + cc;
                int s = r & (SEQ - 1);
                int p = (col & 127) >> 1;
                float c  = fc[s * 64 + p];
                float si = fs[s * 64 + p];
                float re = e * c - o * si;
                float ro = e * si + o * c;
                uint32_t hi, lo;
                split2h(re, ro, hi, lo);
                size_t idx = (size_t)r * QE + col;
                *(uint32_t*)(qh2 + idx) = hi;
                *(uint32_t*)(ql2 + idx) = lo;
            });
    } else if (bx < 20) {
        const int n0 = (bx - 16) * 128;
        gemm16_body<64>(x2, K2, wkh, m0, n0,
            [&](int r, int cc, float e, float o) {
                int col = n0 + cc;
                int s = r & (SEQ - 1);
                int p = (col & 127) >> 1;
                float c  = fc[s * 64 + p];
                float si = fs[s * 64 + p];
                float re = e * c - o * si;
                float ro = e * si + o * c;
                *(uint32_t*)(kh2 + (size_t)r * KVE + col) = pack_f16(re, ro);
            });
    } else {
        const int n0 = (bx - 20) * 128;
        gemm16_body<64>(x2, K2, wvh, m0, n0,
            [&](int r, int cc, float e, float o) {
                *(uint32_t*)(vh2 + (size_t)r * KVE + n0 + cc) = pack_f16(e, o);
            });
    }
}

// ============================================================================
// output projection: 1-term
// ============================================================================
__global__ __launch_bounds__(128, 2)
void wo_gemm(const __half* __restrict__ aoh, const __half* __restrict__ woh,
             float* __restrict__ out)
{
    const int n0 = blockIdx.x * 128;
    const int m0 = blockIdx.y * 128;
    gemm16_body<64>(aoh, QE, woh, m0, n0,
        [&](int r, int cc, float e, float o) {
            *(float2*)(out + (size_t)r * DMODEL + n0 + cc) = make_float2(e, o);
        });
}

// ============================================================================
// attention v2: Br=64, 4 warps/CTA, 3-stage KV ring in 104448 B smem
// -> 2 CTAs/SM. Q tile (hi+lo, 64 rows) loads into stage 0, hoisted to regs,
// then its smem becomes part of the KV ring. Per-row math identical to R15.
// ============================================================================
constexpr int ROWB   = 272;                  // 136 halves per row
constexpr int KTILE  = 64 * ROWB;            // 17408
constexpr int KVSTAGE = 2 * KTILE;           // 34816 (K + V)
constexpr int ATT_SMEM = 3 * KVSTAGE;        // 104448

__global__ __launch_bounds__(128, 2)
void attn_mma(const __half* __restrict__ Qh, const __half* __restrict__ Ql,
              const __half* __restrict__ Kh, const __half* __restrict__ Vh,
              __half* __restrict__ aoh)
{
    extern __shared__ char sm[];
    const uint32_t sb = smem_u32(sm);

    const int qb = gridDim.x - 1 - blockIdx.x;   // heavy blocks first
    const int h  = blockIdx.y;
    const int b  = blockIdx.z;
    const int kh = h >> 2;
    const int tid = threadIdx.x;
    const int wid = tid >> 5;          // 0..3
    const int lane = tid & 31;
    const int q0 = qb * 64;
    const int nkb = qb + 1;

    const int grp = lane >> 3, lr = lane & 7;

    // ---- load Q (hi into [0,17408), lo into [17408,34816)) ----
    {
        const size_t qrow = ((size_t)(b * SEQ + q0) * NH + h) * HD;
        for (int i = tid; i < 1024; i += 128) {
            int r = i >> 4, ch = i & 15;
            size_t g = qrow + (size_t)r * NH * HD + ch * 8;
            uint32_t so = r * ROWB + ch * 16;
            cp16(sb + so,         Qh + g);
            cp16(sb + KTILE + so, Ql + g);
        }
    }
    asm volatile("cp.async.commit_group;" ::: "memory");
    asm volatile("cp.async.wait_group 0;" ::: "memory");
    __syncthreads();

    uint32_t qh_r[8][4], ql_r[8][4];
    {
        const uint32_t qa_h = sb + (wid * 16 + (grp & 1) * 8 + lr) * ROWB
                            + (grp >> 1) * 16;
        const uint32_t qa_l = qa_h + KTILE;
        #pragma unroll
        for (int ks = 0; ks < 8; ks++) {
            ldsm_x4(qh_r[ks], qa_h + ks * 32);
            ldsm_x4(ql_r[ks], qa_l + ks * 32);
        }
    }
    __syncthreads();   // all warps hoisted Q before KV overwrites stage 0

    auto issue_kv = [&](int kb) {
        const uint32_t st = sb + (kb % 3) * KVSTAGE;
        const size_t kvrow = ((size_t)(b * SEQ + kb * 64) * NKV + kh) * HD;
        for (int i = tid; i < 1024; i += 128) {
            int r = i >> 4, ch = i & 15;
            size_t g = kvrow + (size_t)r * NKV * HD + ch * 8;
            uint32_t so = r * ROWB + ch * 16;
            cp16(st + so,         Kh + g);
            cp16(st + KTILE + so, Vh + g);
        }
    };

    issue_kv(0);
    asm volatile("cp.async.commit_group;" ::: "memory");
    if (nkb > 1) issue_kv(1);
    asm volatile("cp.async.commit_group;" ::: "memory");

    const uint32_t kboff = ((grp >> 1) * 8 + lr) * ROWB + (grp & 1) * 16;
    const uint32_t vboff = ((grp & 1) * 8 + lr) * ROWB + (grp >> 1) * 16;

    float m_[2] = {-1e30f, -1e30f};
    float l_[2] = {0.f, 0.f};
    float of[16][4];
    #pragma unroll
    for (int nf = 0; nf < 16; nf++)
        #pragma unroll
        for (int e = 0; e < 4; e++) of[nf][e] = 0.f;

    const float scale = 0.08838834764831845f;
    const int rbase = q0 + wid * 16 + (lane >> 2);

    for (int kb = 0; kb < nkb; kb++) {
        asm volatile("cp.async.wait_group 1;" ::: "memory");  // stage kb done
        __syncthreads();   // visible to all; stage kb-1 fully consumed
        if (kb + 2 < nkb) issue_kv(kb + 2);   // overwrites stage (kb-1)%3
        asm volatile("cp.async.commit_group;" ::: "memory");

        const uint32_t st = sb + (kb % 3) * KVSTAGE;

        // ---- S = Q K^T (Q frags in regs, double-buffered K frags) ----
        float sf[8][4];
        #pragma unroll
        for (int f = 0; f < 8; f++)
            #pragma unroll
            for (int e = 0; e < 4; e++) sf[f][e] = 0.f;

        {
            uint32_t bh0[4], bh1[4];
            ldsm_x4(bh0, st + kboff);
            #pragma unroll
            for (int t = 0; t < 32; t++) {
                const int ks = t >> 2, nb = t & 3;
                uint32_t* cur = (t & 1) ? bh1 : bh0;
                uint32_t* nxt = (t & 1) ? bh0 : bh1;
                if (t + 1 < 32) {
                    const int ks2 = (t + 1) >> 2, nb2 = (t + 1) & 3;
                    ldsm_x4(nxt, st + kboff + nb2 * 16 * ROWB + ks2 * 32);
                }
                mma_f16(sf[2 * nb],     qh_r[ks], cur);
                mma_f16(sf[2 * nb + 1], qh_r[ks], cur + 2);
                mma_f16(sf[2 * nb],     ql_r[ks], cur);
                mma_f16(sf[2 * nb + 1], ql_r[ks], cur + 2);
            }
        }

        // ---- scale + mask + online softmax ----
        float mx[2] = {-1e30f, -1e30f};
        #pragma unroll
        for (int f = 0; f < 8; f++)
            #pragma unroll
            for (int e = 0; e < 4; e++) {
                float v = sf[f][e] * scale;
                int col = kb * 64 + f * 8 + ((lane & 3) << 1) + (e & 1);
                int row = rbase + ((e & 2) << 2);
                v = (col > row) ? -1e30f : v;
                sf[f][e] = v;
                mx[e >> 1] = fmaxf(mx[e >> 1], v);
            }
        #pragma unroll
        for (int e = 0; e < 2; e++) {
            mx[e] = fmaxf(mx[e], __shfl_xor_sync(0xffffffffu, mx[e], 1));
            mx[e] = fmaxf(mx[e], __shfl_xor_sync(0xffffffffu, mx[e], 2));
        }
        float mn[2], alp[2], rs[2] = {0.f, 0.f};
        #pragma unroll
        for (int e = 0; e < 2; e++) {
            mn[e]  = fmaxf(m_[e], mx[e]);
            alp[e] = __expf(m_[e] - mn[e]);
            m_[e]  = mn[e];
        }
        #pragma unroll
        for (int f = 0; f < 8; f++)
            #pragma unroll
            for (int e = 0; e < 4; e++) {
                float p = __expf(sf[f][e] - mn[e >> 1]);
                sf[f][e] = p;
                rs[e >> 1] += p;
            }
        #pragma unroll
        for (int e = 0; e < 2; e++) {
            rs[e] += __shfl_xor_sync(0xffffffffu, rs[e], 1);
            rs[e] += __shfl_xor_sync(0xffffffffu, rs[e], 2);
            l_[e] = l_[e] * alp[e] + rs[e];
        }
        #pragma unroll
        for (int nf = 0; nf < 16; nf++) {
            of[nf][0] *= alp[0]; of[nf][1] *= alp[0];
            of[nf][2] *= alp[1]; of[nf][3] *= alp[1];
        }

        // ---- O += P V ----
        {
            uint32_t PH[4][4], PL[4][4];
            #pragma unroll
            for (int ks = 0; ks < 4; ks++) {
                split2h(sf[2 * ks][0],     sf[2 * ks][1],     PH[ks][0], PL[ks][0]);
                split2h(sf[2 * ks][2],     sf[2 * ks][3],     PH[ks][1], PL[ks][1]);
                split2h(sf[2 * ks + 1][0], sf[2 * ks + 1][1], PH[ks][2], PL[ks][2]);
                split2h(sf[2 * ks + 1][2], sf[2 * ks + 1][3], PH[ks][3], PL[ks][3]);
            }
            uint32_t vv0[4], vv1[4];
            ldsm_x4_t(vv0, st + KTILE + vboff);
            #pragma unroll
            for (int t = 0; t < 32; t++) {
                const int ks = t >> 3, nb = t & 7;
                uint32_t* cur = (t & 1) ? vv1 : vv0;
                uint32_t* nxt = (t & 1) ? vv0 : vv1;
                if (t + 1 < 32) {
                    const int ks2 = (t + 1) >> 3, nb2 = (t + 1) & 7;
                    ldsm_x4_t(nxt, st + KTILE + vboff + ks2 * 16 * ROWB + nb2 * 32);
                }
                mma_f16(of[2 * nb],     PH[ks], cur);
                mma_f16(of[2 * nb + 1], PH[ks], cur + 2);
                mma_f16(of[2 * nb],     PL[ks], cur);
                mma_f16(of[2 * nb + 1], PL[ks], cur + 2);
            }
        }
    }

    // ---- epilogue: normalize, write hi only ----
    float inv0 = 1.f / l_[0], inv1 = 1.f / l_[1];
    size_t b0 = (size_t)(b * SEQ + rbase) * QE + h * HD + ((lane & 3) << 1);
    size_t b1 = b0 + (size_t)8 * QE;
    #pragma unroll
    for (int nf = 0; nf < 16; nf++) {
        *(uint32_t*)(aoh + b0 + nf * 8) = pack_f16(of[nf][0] * inv0, of[nf][1] * inv0);
        *(uint32_t*)(aoh + b1 + nf * 8) = pack_f16(of[nf][2] * inv1, of[nf][3] * inv1);
    }
}

// ============================================================================
// host launcher
// ============================================================================
extern "C" void kernel_launch(void* const* d_in, const int* in_sizes, int n_in,
                              void* d_out, int out_size)
{
    const float* x  = (const float*)d_in[0];
    const float* fc = (const float*)d_in[1];
    const float* fs = (const float*)d_in[2];
    const float* wq = (const float*)d_in[4];
    const float* wk = (const float*)d_in[5];
    const float* wv = (const float*)d_in[6];
    const float* wo = (const float*)d_in[7];
    float* out = (float*)d_out;

    __half *x2, *aoh, *wqh, *wkh, *wvh, *woh, *qh2, *ql2, *kh2, *vh2;
    cudaGetSymbolAddress((void**)&x2,  g_x2);
    cudaGetSymbolAddress((void**)&aoh, g_aoh);
    cudaGetSymbolAddress((void**)&wqh, g_wqh);
    cudaGetSymbolAddress((void**)&wkh, g_wkh);
    cudaGetSymbolAddress((void**)&wvh, g_wvh);
    cudaGetSymbolAddress((void**)&woh, g_woh);
    cudaGetSymbolAddress((void**)&qh2, g_qh2);
    cudaGetSymbolAddress((void**)&ql2, g_ql2);
    cudaGetSymbolAddress((void**)&kh2, g_kh2);
    cudaGetSymbolAddress((void**)&vh2, g_vh2);

    cudaFuncSetAttribute(qkv_gemm, cudaFuncAttributeMaxDynamicSharedMemorySize,
                         GEMM16_SMEM);
    cudaFuncSetAttribute(wo_gemm, cudaFuncAttributeMaxDynamicSharedMemorySize,
                         GEMM16_SMEM);
    cudaFuncSetAttribute(attn_mma, cudaFuncAttributeMaxDynamicSharedMemorySize,
                         ATT_SMEM);

    // ---- single merged conversion launch ----
    convert_all<<<(unsigned)(CQ_WO / 256), 256>>>(
        (const float4*)x, (const float4*)wq, (const float4*)wk,
        (const float4*)wv, (const float4*)wo, x2, wqh, wkh, wvh, woh);

    // ---- fused QKV projection + RoPE + fp16 split ----
    qkv_gemm<<<dim3(24, MROWS / 128), 128, GEMM16_SMEM>>>(
        x2, wqh, wkh, wvh, fc, fs, qh2, ql2, kh2, vh2);

    // ---- tensor-core causal attention (Br=64, 2 CTAs/SM) ----
    attn_mma<<<dim3(SEQ / 64, NH, BB), 128, ATT_SMEM>>>(qh2, ql2, kh2, vh2, aoh);

    // ---- output projection (1-term) ----
    wo_gemm<<<dim3(DMODEL / 128, MROWS / 128), 128, GEMM16_SMEM>>>(aoh, woh, out);
}

// round 17
// speedup vs baseline: 1.6263x; 1.1666x over previous
#include <cuda_runtime.h>
#include <cuda_fp16.h>
#include <math.h>
#include <cstdint>

// ---------------- problem constants ----------------
constexpr int BB     = 2;
constexpr int SEQ    = 2048;
constexpr int DMODEL = 2048;
constexpr int NH     = 16;
constexpr int NKV    = 4;
constexpr int HD     = 128;
constexpr int MROWS  = BB * SEQ;     // 4096
constexpr int QE     = NH * HD;      // 2048
constexpr int KVE    = NKV * HD;     // 512
constexpr int K2     = 4096;         // x stored [hi(2048) | lo(2048)] (lo now unused)

// ---------------- scratch ----------------
__device__ __half g_x2 [(size_t)MROWS * K2];
__device__ __half g_aoh[(size_t)MROWS * QE];
__device__ __half g_wqh[(size_t)QE     * DMODEL];
__device__ __half g_wkh[(size_t)KVE    * DMODEL];
__device__ __half g_wvh[(size_t)KVE    * DMODEL];
__device__ __half g_woh[(size_t)DMODEL * DMODEL];

__device__ __half g_qh2[(size_t)MROWS * QE];
__device__ __half g_ql2[(size_t)MROWS * QE];
__device__ __half g_kh2[(size_t)MROWS * KVE];
__device__ __half g_vh2[(size_t)MROWS * KVE];

// ---------------- helpers ----------------
__device__ __forceinline__ uint32_t smem_u32(const void* p) {
    uint32_t a;
    asm("{ .reg .u64 t; cvta.to.shared.u64 t, %1; cvt.u32.u64 %0, t; }"
        : "=r"(a) : "l"(p));
    return a;
}
__device__ __forceinline__ void cp16(uint32_t dst, const void* src) {
    asm volatile("cp.async.cg.shared.global [%0], [%1], 16;"
                 :: "r"(dst), "l"(src));
}
__device__ __forceinline__ void ldsm_x4(uint32_t* r, uint32_t addr) {
    asm volatile("ldmatrix.sync.aligned.m8n8.x4.shared.b16 {%0,%1,%2,%3}, [%4];"
                 : "=r"(r[0]), "=r"(r[1]), "=r"(r[2]), "=r"(r[3]) : "r"(addr));
}
__device__ __forceinline__ void ldsm_x4_t(uint32_t* r, uint32_t addr) {
    asm volatile("ldmatrix.sync.aligned.m8n8.x4.trans.shared.b16 {%0,%1,%2,%3}, [%4];"
                 : "=r"(r[0]), "=r"(r[1]), "=r"(r[2]), "=r"(r[3]) : "r"(addr));
}
__device__ __forceinline__ void mma_f16(float* d, const uint32_t* a,
                                        const uint32_t* b) {
    asm volatile(
        "mma.sync.aligned.m16n8k16.row.col.f32.f16.f16.f32 "
        "{%0,%1,%2,%3}, {%4,%5,%6,%7}, {%8,%9}, {%0,%1,%2,%3};"
        : "+f"(d[0]), "+f"(d[1]), "+f"(d[2]), "+f"(d[3])
        : "r"(a[0]), "r"(a[1]), "r"(a[2]), "r"(a[3]), "r"(b[0]), "r"(b[1]));
}
__device__ __forceinline__ uint32_t pack_f16(float lo, float hi) {
    uint32_t r;
    asm("cvt.rn.f16x2.f32 %0, %1, %2;" : "=r"(r) : "f"(hi), "f"(lo));
    return r;
}
__device__ __forceinline__ void split2h(float x, float y, uint32_t& hi, uint32_t& lo) {
    uint32_t h = pack_f16(x, y);
    __half2 hb = *reinterpret_cast<__half2*>(&h);
    lo = pack_f16(x - __half2float(hb.x), y - __half2float(hb.y));
    hi = h;
}

// ============================================================================
// merged conversion kernel (x lo half no longer needed -> hi only)
// ============================================================================
constexpr size_t CQ_X  = 2097152;
constexpr size_t CQ_WQ = CQ_X  + 1048576;
constexpr size_t CQ_WK = CQ_WQ + 262144;
constexpr size_t CQ_WV = CQ_WK + 262144;
constexpr size_t CQ_WO = CQ_WV + 1048576;

__global__ __launch_bounds__(256)
void convert_all(const float4* __restrict__ x,  const float4* __restrict__ wq,
                 const float4* __restrict__ wk, const float4* __restrict__ wv,
                 const float4* __restrict__ wo,
                 __half* __restrict__ x2,  __half* __restrict__ wqh,
                 __half* __restrict__ wkh, __half* __restrict__ wvh,
                 __half* __restrict__ woh)
{
    size_t i = (size_t)blockIdx.x * 256 + threadIdx.x;
    if (i < CQ_X) {
        float4 v = x[i];
        size_t e = i * 4;
        size_t r = e >> 11;
        int    c = (int)(e & 2047);
        __half* d = x2 + r * (size_t)K2 + c;
        d[0] = __float2half(v.x);
        d[1] = __float2half(v.y);
        d[2] = __float2half(v.z);
        d[3] = __float2half(v.w);
        return;
    }
    const float4* src; __half* dst; size_t j;
    if      (i < CQ_WQ) { src = wq; dst = wqh; j = i - CQ_X;  }
    else if (i < CQ_WK) { src = wk; dst = wkh; j = i - CQ_WQ; }
    else if (i < CQ_WV) { src = wv; dst = wvh; j = i - CQ_WK; }
    else                { src = wo; dst = woh; j = i - CQ_WV; }
    float4 v = src[j];
    size_t e = j * 4;
    dst[e]     = __float2half(v.x);
    dst[e + 1] = __float2half(v.y);
    dst[e + 2] = __float2half(v.z);
    dst[e + 3] = __float2half(v.w);
}

// ============================================================================
// GEMM (unchanged): 4 warps, 64x64 warp tiles, templated chunk count
// ============================================================================
constexpr int HROWB  = 80;
constexpr int GTILE  = 128 * HROWB;        // 10240 B
constexpr int GSTAGE = 2 * GTILE;
constexpr int GEMM16_SMEM = 4 * GSTAGE;    // 81920

template <int NCH_T, typename EPI>
__device__ __forceinline__
void gemm16_body(const __half* __restrict__ A, int a_stride,
                 const __half* __restrict__ Bw,
                 int m0, int n0loc, EPI epi)
{
    extern __shared__ char sm[];
    const uint32_t sb = smem_u32(sm);
    const int tid = threadIdx.x;
    const int wid = tid >> 5;
    const int lane = tid & 31;
    const int wm = (wid >> 1) * 64;
    const int wn = (wid & 1) * 64;

    const __half* Abase = A  + (size_t)m0 * a_stride;
    const __half* Bbase = Bw + (size_t)n0loc * DMODEL;

    const int grp = lane >> 3, lr = lane & 7;
    const uint32_t aoff0 = (wm + (grp & 1) * 8 + lr) * HROWB + (grp >> 1) * 16;
    const uint32_t boff0 = GTILE + (wn + (grp >> 1) * 8 + lr) * HROWB
                         + (grp & 1) * 16;

    float acc[4][8][4];
    #pragma unroll
    for (int mf = 0; mf < 4; mf++)
        #pragma unroll
        for (int nf = 0; nf < 8; nf++)
            #pragma unroll
            for (int e = 0; e < 4; e++) acc[mf][nf][e] = 0.f;

    auto issue = [&](int c) {
        if (c >= NCH_T) return;
        const uint32_t st = sb + (c & 3) * GSTAGE;
        const __half* Ag = Abase + c * 32;
        const __half* Bg = Bbase + (c & 63) * 32;
        #pragma unroll
        for (int t = 0; t < 4; t++) {
            int i = tid + t * 128;
            int row = i >> 2, seg = i & 3;
            cp16(st + row * HROWB + seg * 16,
                 Ag + (size_t)row * a_stride + seg * 8);
        }
        #pragma unroll
        for (int t = 0; t < 4; t++) {
            int i = tid + t * 128;
            int row = i >> 2, seg = i & 3;
            cp16(st + GTILE + row * HROWB + seg * 16,
                 Bg + (size_t)row * DMODEL + seg * 8);
        }
    };

    issue(0); asm volatile("cp.async.commit_group;" ::: "memory");
    issue(1); asm volatile("cp.async.commit_group;" ::: "memory");
    issue(2); asm volatile("cp.async.commit_group;" ::: "memory");

    uint32_t arA[4][4], brA[4][4], arB[4][4], brB[4][4];

    for (int c = 0; c < NCH_T; c++) {
        asm volatile("cp.async.wait_group 2;" ::: "memory");
        __syncthreads();
        issue(c + 3);
        asm volatile("cp.async.commit_group;" ::: "memory");

        const uint32_t st = sb + (c & 3) * GSTAGE;

        #pragma unroll
        for (int mf = 0; mf < 4; mf++)
            ldsm_x4(arA[mf], st + aoff0 + mf * (16 * HROWB));
        #pragma unroll
        for (int nf2 = 0; nf2 < 4; nf2++)
            ldsm_x4(brA[nf2], st + boff0 + nf2 * (16 * HROWB));

        #pragma unroll
        for (int mf = 0; mf < 4; mf++) {
            ldsm_x4(arB[mf], st + aoff0 + mf * (16 * HROWB) + 32);
            #pragma unroll
            for (int nf = 0; nf < 4; nf++)
                mma_f16(acc[mf][nf], arA[mf], &brA[nf >> 1][(nf & 1) * 2]);
            ldsm_x4(brB[mf], st + boff0 + mf * (16 * HROWB) + 32);
            #pragma unroll
            for (int nf = 4; nf < 8; nf++)
                mma_f16(acc[mf][nf], arA[mf], &brA[nf >> 1][(nf & 1) * 2]);
        }

        #pragma unroll
        for (int mf = 0; mf < 4; mf++)
            #pragma unroll
            for (int nf = 0; nf < 8; nf++)
                mma_f16(acc[mf][nf], arB[mf], &brB[nf >> 1][(nf & 1) * 2]);
    }

    const int lr4 = lane >> 2, lc2 = (lane & 3) * 2;
    #pragma unroll
    for (int mf = 0; mf < 4; mf++) {
        int r = m0 + wm + mf * 16 + lr4;
        #pragma unroll
        for (int nf = 0; nf < 8; nf++) {
            int cc = wn + nf * 8 + lc2;
            epi(r,     cc, acc[mf][nf][0], acc[mf][nf][1]);
            epi(r + 8, cc, acc[mf][nf][2], acc[mf][nf][3]);
        }
    }
}

// ============================================================================
// fused QKV projection: all 1-term now (Q lo dropped)
// ============================================================================
__global__ __launch_bounds__(128, 2)
void qkv_gemm(const __half* __restrict__ x2,
              const __half* __restrict__ wqh, const __half* __restrict__ wkh,
              const __half* __restrict__ wvh,
              const float* __restrict__ fc, const float* __restrict__ fs,
              __half* __restrict__ qh2, __half* __restrict__ ql2,
              __half* __restrict__ kh2, __half* __restrict__ vh2)
{
    const int bx = blockIdx.x;
    const int m0 = blockIdx.y * 128;

    if (bx < 16) {             // Q: 1-term projection; output still split hi/lo
        const int n0 = bx * 128;
        gemm16_body<64>(x2, K2, wqh, m0, n0,
            [&](int r, int cc, float e, float o) {
                int col = n0 + cc;
                int s = r & (SEQ - 1);
                int p = (col & 127) >> 1;
                float c  = fc[s * 64 + p];
                float si = fs[s * 64 + p];
                float re = e * c - o * si;
                float ro = e * si + o * c;
                uint32_t hi, lo;
                split2h(re, ro, hi, lo);
                size_t idx = (size_t)r * QE + col;
                *(uint32_t*)(qh2 + idx) = hi;
                *(uint32_t*)(ql2 + idx) = lo;
            });
    } else if (bx < 20) {      // K: 1-term
        const int n0 = (bx - 16) * 128;
        gemm16_body<64>(x2, K2, wkh, m0, n0,
            [&](int r, int cc, float e, float o) {
                int col = n0 + cc;
                int s = r & (SEQ - 1);
                int p = (col & 127) >> 1;
                float c  = fc[s * 64 + p];
                float si = fs[s * 64 + p];
                float re = e * c - o * si;
                float ro = e * si + o * c;
                *(uint32_t*)(kh2 + (size_t)r * KVE + col) = pack_f16(re, ro);
            });
    } else {                   // V: 1-term
        const int n0 = (bx - 20) * 128;
        gemm16_body<64>(x2, K2, wvh, m0, n0,
            [&](int r, int cc, float e, float o) {
                *(uint32_t*)(vh2 + (size_t)r * KVE + n0 + cc) = pack_f16(e, o);
            });
    }
}

// ============================================================================
// output projection: 1-term
// ============================================================================
__global__ __launch_bounds__(128, 2)
void wo_gemm(const __half* __restrict__ aoh, const __half* __restrict__ woh,
             float* __restrict__ out)
{
    const int n0 = blockIdx.x * 128;
    const int m0 = blockIdx.y * 128;
    gemm16_body<64>(aoh, QE, woh, m0, n0,
        [&](int r, int cc, float e, float o) {
            *(float2*)(out + (size_t)r * DMODEL + n0 + cc) = make_float2(e, o);
        });
}

// ============================================================================
// attention: Br=64, 4 warps, 3-stage KV ring, 2 CTAs/SM (unchanged from R16)
// ============================================================================
constexpr int ROWB   = 272;
constexpr int KTILE  = 64 * ROWB;            // 17408
constexpr int KVSTAGE = 2 * KTILE;           // 34816
constexpr int ATT_SMEM = 3 * KVSTAGE;        // 104448

__global__ __launch_bounds__(128, 2)
void attn_mma(const __half* __restrict__ Qh, const __half* __restrict__ Ql,
              const __half* __restrict__ Kh, const __half* __restrict__ Vh,
              __half* __restrict__ aoh)
{
    extern __shared__ char sm[];
    const uint32_t sb = smem_u32(sm);

    const int qb = gridDim.x - 1 - blockIdx.x;
    const int h  = blockIdx.y;
    const int b  = blockIdx.z;
    const int kh = h >> 2;
    const int tid = threadIdx.x;
    const int wid = tid >> 5;
    const int lane = tid & 31;
    const int q0 = qb * 64;
    const int nkb = qb + 1;

    const int grp = lane >> 3, lr = lane & 7;

    {
        const size_t qrow = ((size_t)(b * SEQ + q0) * NH + h) * HD;
        for (int i = tid; i < 1024; i += 128) {
            int r = i >> 4, ch = i & 15;
            size_t g = qrow + (size_t)r * NH * HD + ch * 8;
            uint32_t so = r * ROWB + ch * 16;
            cp16(sb + so,         Qh + g);
            cp16(sb + KTILE + so, Ql + g);
        }
    }
    asm volatile("cp.async.commit_group;" ::: "memory");
    asm volatile("cp.async.wait_group 0;" ::: "memory");
    __syncthreads();

    uint32_t qh_r[8][4], ql_r[8][4];
    {
        const uint32_t qa_h = sb + (wid * 16 + (grp & 1) * 8 + lr) * ROWB
                            + (grp >> 1) * 16;
        const uint32_t qa_l = qa_h + KTILE;
        #pragma unroll
        for (int ks = 0; ks < 8; ks++) {
            ldsm_x4(qh_r[ks], qa_h + ks * 32);
            ldsm_x4(ql_r[ks], qa_l + ks * 32);
        }
    }
    __syncthreads();

    auto issue_kv = [&](int kb) {
        const uint32_t st = sb + (kb % 3) * KVSTAGE;
        const size_t kvrow = ((size_t)(b * SEQ + kb * 64) * NKV + kh) * HD;
        for (int i = tid; i < 1024; i += 128) {
            int r = i >> 4, ch = i & 15;
            size_t g = kvrow + (size_t)r * NKV * HD + ch * 8;
            uint32_t so = r * ROWB + ch * 16;
            cp16(st + so,         Kh + g);
            cp16(st + KTILE + so, Vh + g);
        }
    };

    issue_kv(0);
    asm volatile("cp.async.commit_group;" ::: "memory");
    if (nkb > 1) issue_kv(1);
    asm volatile("cp.async.commit_group;" ::: "memory");

    const uint32_t kboff = ((grp >> 1) * 8 + lr) * ROWB + (grp & 1) * 16;
    const uint32_t vboff = ((grp & 1) * 8 + lr) * ROWB + (grp >> 1) * 16;

    float m_[2] = {-1e30f, -1e30f};
    float l_[2] = {0.f, 0.f};
    float of[16][4];
    #pragma unroll
    for (int nf = 0; nf < 16; nf++)
        #pragma unroll
        for (int e = 0; e < 4; e++) of[nf][e] = 0.f;

    const float scale = 0.08838834764831845f;
    const int rbase = q0 + wid * 16 + (lane >> 2);

    for (int kb = 0; kb < nkb; kb++) {
        asm volatile("cp.async.wait_group 1;" ::: "memory");
        __syncthreads();
        if (kb + 2 < nkb) issue_kv(kb + 2);
        asm volatile("cp.async.commit_group;" ::: "memory");

        const uint32_t st = sb + (kb % 3) * KVSTAGE;

        float sf[8][4];
        #pragma unroll
        for (int f = 0; f < 8; f++)
            #pragma unroll
            for (int e = 0; e < 4; e++) sf[f][e] = 0.f;

        {
            uint32_t bh0[4], bh1[4];
            ldsm_x4(bh0, st + kboff);
            #pragma unroll
            for (int t = 0; t < 32; t++) {
                const int ks = t >> 2, nb = t & 3;
                uint32_t* cur = (t & 1) ? bh1 : bh0;
                uint32_t* nxt = (t & 1) ? bh0 : bh1;
                if (t + 1 < 32) {
                    const int ks2 = (t + 1) >> 2, nb2 = (t + 1) & 3;
                    ldsm_x4(nxt, st + kboff + nb2 * 16 * ROWB + ks2 * 32);
                }
                mma_f16(sf[2 * nb],     qh_r[ks], cur);
                mma_f16(sf[2 * nb + 1], qh_r[ks], cur + 2);
                mma_f16(sf[2 * nb],     ql_r[ks], cur);
                mma_f16(sf[2 * nb + 1], ql_r[ks], cur + 2);
            }
        }

        float mx[2] = {-1e30f, -1e30f};
        #pragma unroll
        for (int f = 0; f < 8; f++)
            #pragma unroll
            for (int e = 0; e < 4; e++) {
                float v = sf[f][e] * scale;
                int col = kb * 64 + f * 8 + ((lane & 3) << 1) + (e & 1);
                int row = rbase + ((e & 2) << 2);
                v = (col > row) ? -1e30f : v;
                sf[f][e] = v;
                mx[e >> 1] = fmaxf(mx[e >> 1], v);
            }
        #pragma unroll
        for (int e = 0; e < 2; e++) {
            mx[e] = fmaxf(mx[e], __shfl_xor_sync(0xffffffffu, mx[e], 1));
            mx[e] = fmaxf(mx[e], __shfl_xor_sync(0xffffffffu, mx[e], 2));
        }
        float mn[2], alp[2], rs[2] = {0.f, 0.f};
        #pragma unroll
        for (int e = 0; e < 2; e++) {
            mn[e]  = fmaxf(m_[e], mx[e]);
            alp[e] = __expf(m_[e] - mn[e]);
            m_[e]  = mn[e];
        }
        #pragma unroll
        for (int f = 0; f < 8; f++)
            #pragma unroll
            for (int e = 0; e < 4; e++) {
                float p = __expf(sf[f][e] - mn[e >> 1]);
                sf[f][e] = p;
                rs[e >> 1] += p;
            }
        #pragma unroll
        for (int e = 0; e < 2; e++) {
            rs[e] += __shfl_xor_sync(0xffffffffu, rs[e], 1);
            rs[e] += __shfl_xor_sync(0xffffffffu, rs[e], 2);
            l_[e] = l_[e] * alp[e] + rs[e];
        }
        #pragma unroll
        for (int nf = 0; nf < 16; nf++) {
            of[nf][0] *= alp[0]; of[nf][1] *= alp[0];
            of[nf][2] *= alp[1]; of[nf][3] *= alp[1];
        }

        {
            uint32_t PH[4][4], PL[4][4];
            #pragma unroll
            for (int ks = 0; ks < 4; ks++) {
                split2h(sf[2 * ks][0],     sf[2 * ks][1],     PH[ks][0], PL[ks][0]);
                split2h(sf[2 * ks][2],     sf[2 * ks][3],     PH[ks][1], PL[ks][1]);
                split2h(sf[2 * ks + 1][0], sf[2 * ks + 1][1], PH[ks][2], PL[ks][2]);
                split2h(sf[2 * ks + 1][2], sf[2 * ks + 1][3], PH[ks][3], PL[ks][3]);
            }
            uint32_t vv0[4], vv1[4];
            ldsm_x4_t(vv0, st + KTILE + vboff);
            #pragma unroll
            for (int t = 0; t < 32; t++) {
                const int ks = t >> 3, nb = t & 7;
                uint32_t* cur = (t & 1) ? vv1 : vv0;
                uint32_t* nxt = (t & 1) ? vv0 : vv1;
                if (t + 1 < 32) {
                    const int ks2 = (t + 1) >> 3, nb2 = (t + 1) & 7;
                    ldsm_x4_t(nxt, st + KTILE + vboff + ks2 * 16 * ROWB + nb2 * 32);
                }
                mma_f16(of[2 * nb],     PH[ks], cur);
                mma_f16(of[2 * nb + 1], PH[ks], cur + 2);
                mma_f16(of[2 * nb],     PL[ks], cur);
                mma_f16(of[2 * nb + 1], PL[ks], cur + 2);
            }
        }
    }

    float inv0 = 1.f / l_[0], inv1 = 1.f / l_[1];
    size_t b0 = (size_t)(b * SEQ + rbase) * QE + h * HD + ((lane & 3) << 1);
    size_t b1 = b0 + (size_t)8 * QE;
    #pragma unroll
    for (int nf = 0; nf < 16; nf++) {
        *(uint32_t*)(aoh + b0 + nf * 8) = pack_f16(of[nf][0] * inv0, of[nf][1] * inv0);
        *(uint32_t*)(aoh + b1 + nf * 8) = pack_f16(of[nf][2] * inv1, of[nf][3] * inv1);
    }
}

// ============================================================================
// host launcher
// ============================================================================
extern "C" void kernel_launch(void* const* d_in, const int* in_sizes, int n_in,
                              void* d_out, int out_size)
{
    const float* x  = (const float*)d_in[0];
    const float* fc = (const float*)d_in[1];
    const float* fs = (const float*)d_in[2];
    const float* wq = (const float*)d_in[4];
    const float* wk = (const float*)d_in[5];
    const float* wv = (const float*)d_in[6];
    const float* wo = (const float*)d_in[7];
    float* out = (float*)d_out;

    __half *x2, *aoh, *wqh, *wkh, *wvh, *woh, *qh2, *ql2, *kh2, *vh2;
    cudaGetSymbolAddress((void**)&x2,  g_x2);
    cudaGetSymbolAddress((void**)&aoh, g_aoh);
    cudaGetSymbolAddress((void**)&wqh, g_wqh);
    cudaGetSymbolAddress((void**)&wkh, g_wkh);
    cudaGetSymbolAddress((void**)&wvh, g_wvh);
    cudaGetSymbolAddress((void**)&woh, g_woh);
    cudaGetSymbolAddress((void**)&qh2, g_qh2);
    cudaGetSymbolAddress((void**)&ql2, g_ql2);
    cudaGetSymbolAddress((void**)&kh2, g_kh2);
    cudaGetSymbolAddress((void**)&vh2, g_vh2);

    cudaFuncSetAttribute(qkv_gemm, cudaFuncAttributeMaxDynamicSharedMemorySize,
                         GEMM16_SMEM);
    cudaFuncSetAttribute(wo_gemm, cudaFuncAttributeMaxDynamicSharedMemorySize,
                         GEMM16_SMEM);
    cudaFuncSetAttribute(attn_mma, cudaFuncAttributeMaxDynamicSharedMemorySize,
                         ATT_SMEM);

    // ---- single merged conversion launch ----
    convert_all<<<(unsigned)(CQ_WO / 256), 256>>>(
        (const float4*)x, (const float4*)wq, (const float4*)wk,
        (const float4*)wv, (const float4*)wo, x2, wqh, wkh, wvh, woh);

    // ---- fused QKV projection + RoPE + fp16 split (all 1-term) ----
    qkv_gemm<<<dim3(24, MROWS / 128), 128, GEMM16_SMEM>>>(
        x2, wqh, wkh, wvh, fc, fs, qh2, ql2, kh2, vh2);

    // ---- tensor-core causal attention (Br=64, 2 CTAs/SM) ----
    attn_mma<<<dim3(SEQ / 64, NH, BB), 128, ATT_SMEM>>>(qh2, ql2, kh2, vh2, aoh);

    // ---- output projection (1-term) ----
    wo_gemm<<<dim3(DMODEL / 128, MROWS / 128), 128, GEMM16_SMEM>>>(aoh, woh, out);
}